// round 1
// baseline (speedup 1.0000x reference)
#include <cuda_runtime.h>
#include <cstdint>

// ---------------- problem constants ----------------
#define BATCH 4
#define SEQ   8192
#define DMODEL 512
#define HEADS 8
#define DH    64
#define LM    256          // landmarks
#define LGRP  32           // SEQ / LM
#define NTOK  (BATCH*SEQ)          // 32768
#define BH    (BATCH*HEADS)        // 32
#define KSZ   33

// ---------------- scratch (device globals; no allocation allowed) ----------
__device__ float g_xn   [(size_t)NTOK*DMODEL];        // 64MB
__device__ float g_qkv  [(size_t)NTOK*3*DMODEL];      // 192MB
__device__ float g_q    [(size_t)BH*SEQ*DH];          // 64MB
__device__ float g_k    [(size_t)BH*SEQ*DH];
__device__ float g_v    [(size_t)BH*SEQ*DH];
__device__ float g_ql   [(size_t)BH*LM*DH];           // 2MB
__device__ float g_kl   [(size_t)BH*LM*DH];
__device__ float g_attn1[(size_t)BH*SEQ*LM];          // 256MB
__device__ float g_attn3[(size_t)BH*LM*SEQ];          // 256MB
__device__ float g_attn2[(size_t)BH*LM*LM];           // 8MB
__device__ float g_za   [(size_t)BH*LM*LM];
__device__ float g_zb   [(size_t)BH*LM*LM];
__device__ float g_xz   [(size_t)BH*LM*LM];
__device__ float g_t1   [(size_t)BH*LM*LM];
__device__ float g_t2   [(size_t)BH*LM*LM];
__device__ float g_a3v  [(size_t)BH*LM*DH];           // 2MB
__device__ float g_out1 [(size_t)BH*SEQ*LM];          // 256MB
__device__ float g_outh [(size_t)BH*SEQ*DH];          // 64MB
__device__ float g_tok  [(size_t)NTOK*DMODEL];        // 64MB
__device__ float g_scale[2];

// ---------------- LayerNorm ----------------
__global__ void ln_kernel(const float* __restrict__ x, const float* __restrict__ w,
                          const float* __restrict__ b, float* __restrict__ y)
{
    int row = blockIdx.x;
    int tid = threadIdx.x;                 // 128 threads, 4 elems each
    const float* xr = x + (long long)row * DMODEL;
    float4 v = *(const float4*)(xr + tid * 4);
    float s  = v.x + v.y + v.z + v.w;
    float s2 = v.x*v.x + v.y*v.y + v.z*v.z + v.w*v.w;
    __shared__ float r1[128], r2[128];
    r1[tid] = s; r2[tid] = s2; __syncthreads();
    for (int t = 64; t > 0; t >>= 1) {
        if (tid < t) { r1[tid] += r1[tid+t]; r2[tid] += r2[tid+t]; }
        __syncthreads();
    }
    float mean = r1[0] * (1.0f / DMODEL);
    float var  = r2[0] * (1.0f / DMODEL) - mean * mean;
    float inv  = rsqrtf(var + 1e-5f);
    float4 w4 = *(const float4*)(w + tid * 4);
    float4 b4 = *(const float4*)(b + tid * 4);
    float4 o;
    o.x = (v.x - mean) * inv * w4.x + b4.x;
    o.y = (v.y - mean) * inv * w4.y + b4.y;
    o.z = (v.z - mean) * inv * w4.z + b4.z;
    o.w = (v.w - mean) * inv * w4.w + b4.w;
    *(float4*)(y + (long long)row * DMODEL + tid * 4) = o;
}

// ---------------- big GEMM: 128x128x16 tiles, 8x8 per thread ----------------
// C[M,N] = alpha * A[M,K] * op(B) (+ bias[n]) (+ resid[m,n]); op(B)=B^T if TB (B is [N,K])
template<bool TB>
__global__ void __launch_bounds__(256) gemm_big(
    const float* __restrict__ A, const float* __restrict__ B, float* __restrict__ C,
    int M, int N, int K, long long sA, long long sB, long long sC,
    float alpha, const float* __restrict__ bias, const float* __restrict__ resid)
{
    const int z = blockIdx.z;
    A += z * sA; B += z * sB; C += z * sC;
    if (resid) resid += z * sC;
    __shared__ float As[16][132];
    __shared__ float Bs[16][132];
    const int m0 = blockIdx.y * 128;
    const int n0 = blockIdx.x * 128;
    const int tid = threadIdx.x;
    const int ty = tid >> 4, tx = tid & 15;
    float acc[8][8];
#pragma unroll
    for (int i = 0; i < 8; i++)
#pragma unroll
        for (int j = 0; j < 8; j++) acc[i][j] = 0.f;

    for (int k0 = 0; k0 < K; k0 += 16) {
#pragma unroll
        for (int t = 0; t < 2; ++t) {
            int idx = tid * 2 + t;          // 0..511
            int r   = idx >> 2;             // 0..127
            int kk  = (idx & 3) << 2;       // 0,4,8,12
            float4 va = make_float4(0.f,0.f,0.f,0.f);
            int gm = m0 + r;
            if (gm < M) va = *(const float4*)(A + (long long)gm * K + k0 + kk);
            As[kk+0][r] = va.x; As[kk+1][r] = va.y; As[kk+2][r] = va.z; As[kk+3][r] = va.w;
            if (TB) {
                float4 vb = make_float4(0.f,0.f,0.f,0.f);
                int gn = n0 + r;
                if (gn < N) vb = *(const float4*)(B + (long long)gn * K + k0 + kk);
                Bs[kk+0][r] = vb.x; Bs[kk+1][r] = vb.y; Bs[kk+2][r] = vb.z; Bs[kk+3][r] = vb.w;
            } else {
                int kr = idx >> 5;               // 0..15
                int c  = (idx & 31) << 2;        // 0..124
                float4 vb = make_float4(0.f,0.f,0.f,0.f);
                if (n0 + c < N) vb = *(const float4*)(B + (long long)(k0 + kr) * N + n0 + c);
                *(float4*)&Bs[kr][c] = vb;
            }
        }
        __syncthreads();
#pragma unroll
        for (int k = 0; k < 16; ++k) {
            float a[8], bfr[8];
            *(float4*)&a[0]   = *(const float4*)&As[k][ty*8];
            *(float4*)&a[4]   = *(const float4*)&As[k][ty*8+4];
            *(float4*)&bfr[0] = *(const float4*)&Bs[k][tx*8];
            *(float4*)&bfr[4] = *(const float4*)&Bs[k][tx*8+4];
#pragma unroll
            for (int i = 0; i < 8; i++)
#pragma unroll
                for (int j = 0; j < 8; j++)
                    acc[i][j] += a[i] * bfr[j];
        }
        __syncthreads();
    }
#pragma unroll
    for (int i = 0; i < 8; i++) {
        int gm = m0 + ty*8 + i;
        if (gm >= M) continue;
#pragma unroll
        for (int j = 0; j < 8; j++) {
            int gn = n0 + tx*8 + j;
            if (gn >= N) continue;
            float v = alpha * acc[i][j];
            if (bias)  v += bias[gn];
            if (resid) v += resid[(long long)gm * N + gn];
            C[(long long)gm * N + gn] = v;
        }
    }
}

// ---------------- small GEMM: 64x64x16 tiles, 4x4 per thread, +betaI epilogue ----
template<bool TB>
__global__ void __launch_bounds__(256) gemm_small(
    const float* __restrict__ A, const float* __restrict__ B, float* __restrict__ C,
    int M, int N, int K, long long sA, long long sB, long long sC,
    float alpha, float betaI)
{
    const int z = blockIdx.z;
    A += z * sA; B += z * sB; C += z * sC;
    __shared__ float As[16][68];
    __shared__ float Bs[16][68];
    const int m0 = blockIdx.y * 64;
    const int n0 = blockIdx.x * 64;
    const int tid = threadIdx.x;
    const int ty = tid >> 4, tx = tid & 15;
    float acc[4][4];
#pragma unroll
    for (int i = 0; i < 4; i++)
#pragma unroll
        for (int j = 0; j < 4; j++) acc[i][j] = 0.f;

    for (int k0 = 0; k0 < K; k0 += 16) {
        {
            int idx = tid;                 // 0..255
            int r   = idx >> 2;            // 0..63
            int kk  = (idx & 3) << 2;
            float4 va = make_float4(0.f,0.f,0.f,0.f);
            int gm = m0 + r;
            if (gm < M) va = *(const float4*)(A + (long long)gm * K + k0 + kk);
            As[kk+0][r] = va.x; As[kk+1][r] = va.y; As[kk+2][r] = va.z; As[kk+3][r] = va.w;
            if (TB) {
                float4 vb = make_float4(0.f,0.f,0.f,0.f);
                int gn = n0 + r;
                if (gn < N) vb = *(const float4*)(B + (long long)gn * K + k0 + kk);
                Bs[kk+0][r] = vb.x; Bs[kk+1][r] = vb.y; Bs[kk+2][r] = vb.z; Bs[kk+3][r] = vb.w;
            } else {
                int kr = idx >> 4;              // 0..15
                int c  = (idx & 15) << 2;       // 0..60
                float4 vb = make_float4(0.f,0.f,0.f,0.f);
                if (n0 + c < N) vb = *(const float4*)(B + (long long)(k0 + kr) * N + n0 + c);
                *(float4*)&Bs[kr][c] = vb;
            }
        }
        __syncthreads();
#pragma unroll
        for (int k = 0; k < 16; ++k) {
            float a[4], bfr[4];
            *(float4*)&a[0]   = *(const float4*)&As[k][ty*4];
            *(float4*)&bfr[0] = *(const float4*)&Bs[k][tx*4];
#pragma unroll
            for (int i = 0; i < 4; i++)
#pragma unroll
                for (int j = 0; j < 4; j++)
                    acc[i][j] += a[i] * bfr[j];
        }
        __syncthreads();
    }
#pragma unroll
    for (int i = 0; i < 4; i++) {
        int gm = m0 + ty*4 + i;
        if (gm >= M) continue;
#pragma unroll
        for (int j = 0; j < 4; j++) {
            int gn = n0 + tx*4 + j;
            if (gn >= N) continue;
            float v = alpha * acc[i][j];
            if (gm == gn) v += betaI;
            C[(long long)gm * N + gn] = v;
        }
    }
}

// ---------------- split qkv into per-head q(scaled), k, v ----------------
__global__ void split_qkv(const float* __restrict__ QKV, float* __restrict__ Q,
                          float* __restrict__ K, float* __restrict__ V)
{
    long long idx = (long long)blockIdx.x * 256 + threadIdx.x;   // NTOK*DMODEL total
    int c = idx & 63;
    int h = (int)((idx >> 6) & 7);
    long long tok = idx >> 9;
    int i = (int)(tok & (SEQ - 1));
    int b = (int)(tok >> 13);
    long long dst = (((long long)(b * HEADS + h) * SEQ) + i) * DH + c;
    long long src = tok * (3 * DMODEL) + h * DH + c;
    Q[dst] = QKV[src] * 0.125f;             // dh^-0.5
    K[dst] = QKV[src + DMODEL];
    V[dst] = QKV[src + 2 * DMODEL];
}

// ---------------- landmark means (contiguous groups of 32) ----------------
__global__ void landmark(const float* __restrict__ Q, float* __restrict__ QL)
{
    int idx = blockIdx.x * 256 + threadIdx.x;      // BH*LM*DH = 524288
    int c  = idx & 63;
    int m  = (idx >> 6) & 255;
    int bh = idx >> 14;
    const float* p = Q + ((long long)bh * SEQ + m * LGRP) * DH + c;
    float s = 0.f;
#pragma unroll
    for (int t = 0; t < LGRP; ++t) s += p[t * DH];
    QL[idx] = s * (1.f / LGRP);
}

// ---------------- row softmax (W = E*256) ----------------
template<int E>
__global__ void softmax_rows(float* __restrict__ S)
{
    const int W = E * 256;
    float* row = S + (long long)blockIdx.x * W;
    int tid = threadIdx.x;
    float v[E];
    float mx = -1e30f;
#pragma unroll
    for (int i = 0; i < E; i++) { v[i] = row[tid + i * 256]; mx = fmaxf(mx, v[i]); }
    __shared__ float red[256];
    red[tid] = mx; __syncthreads();
    for (int t = 128; t > 0; t >>= 1) {
        if (tid < t) red[tid] = fmaxf(red[tid], red[tid + t]);
        __syncthreads();
    }
    mx = red[0]; __syncthreads();
    float sm = 0.f;
#pragma unroll
    for (int i = 0; i < E; i++) { v[i] = __expf(v[i] - mx); sm += v[i]; }
    red[tid] = sm; __syncthreads();
    for (int t = 128; t > 0; t >>= 1) {
        if (tid < t) red[tid] += red[tid + t];
        __syncthreads();
    }
    float inv = 1.f / red[0];
#pragma unroll
    for (int i = 0; i < E; i++) row[tid + i * 256] = v[i] * inv;
}

// ---------------- pinv scale: global max row-sum and col-sum of |attn2| -----
__global__ void scale_init(float* s) { s[0] = 0.f; s[1] = 0.f; }

__global__ void colrow_max(const float* __restrict__ A2, float* __restrict__ s)
{
    int bh = blockIdx.x, j = threadIdx.x;
    const float* X = A2 + (long long)bh * LM * LM;
    float cs = 0.f, rs = 0.f;
    for (int i = 0; i < LM; ++i) {
        cs += fabsf(X[i * LM + j]);
        rs += fabsf(X[j * LM + i]);
    }
    __shared__ float r1[256], r2[256];
    r1[j] = cs; r2[j] = rs; __syncthreads();
    for (int t = 128; t > 0; t >>= 1) {
        if (j < t) { r1[j] = fmaxf(r1[j], r1[j+t]); r2[j] = fmaxf(r2[j], r2[j+t]); }
        __syncthreads();
    }
    if (j == 0) {
        atomicMax((int*)&s[0], __float_as_int(r1[0]));
        atomicMax((int*)&s[1], __float_as_int(r2[0]));
    }
}

// Z0 = attn2^T / (colmax*rowmax)
__global__ void make_z0(const float* __restrict__ A2, const float* __restrict__ s,
                        float* __restrict__ Z)
{
    long long idx = (long long)blockIdx.x * 256 + threadIdx.x;   // BH*LM*LM
    int c  = idx & 255;
    int r  = (int)((idx >> 8) & 255);
    int bh = (int)(idx >> 16);
    float inv = 1.f / (s[0] * s[1]);
    Z[idx] = A2[(long long)bh * LM * LM + (long long)c * LM + r] * inv;
}

// T = beta*I - XZ  (elementwise)
__global__ void diag_sub(const float* __restrict__ XZ, float* __restrict__ T, float beta)
{
    long long idx = (long long)blockIdx.x * 256 + threadIdx.x;
    int c = idx & 255;
    int r = (int)((idx >> 8) & 255);
    T[idx] = (r == c ? beta : 0.f) - XZ[idx];
}

// ---------------- depthwise conv-33 over seq + combine + token-major write ----
__global__ void __launch_bounds__(256) conv_combine(
    const float* __restrict__ V, const float* __restrict__ O,
    const float* __restrict__ cw, float* __restrict__ TOK)
{
    int bh = blockIdx.y;
    int h = bh & 7, b = bh >> 3;
    int i0 = blockIdx.x * 64;
    __shared__ float sv[96][64];
    __shared__ float w[KSZ];
    int tid = threadIdx.x;
    if (tid < KSZ) w[tid] = cw[h * KSZ + tid];
    const float* Vb = V + (long long)bh * SEQ * DH;
    for (int e = tid; e < 96 * 64; e += 256) {
        int rr = e >> 6, c = e & 63;
        int gi = i0 - 16 + rr;
        sv[rr][c] = (gi >= 0 && gi < SEQ) ? Vb[(long long)gi * DH + c] : 0.f;
    }
    __syncthreads();
    int c  = tid & 63;
    int ib = tid >> 6;          // 0..3
#pragma unroll 4
    for (int j = 0; j < 16; ++j) {
        int il = ib * 16 + j;
        float acc = O[((long long)bh * SEQ + i0 + il) * DH + c];
#pragma unroll
        for (int t = 0; t < KSZ; ++t) acc += w[t] * sv[il + t][c];
        long long tok = (long long)b * SEQ + i0 + il;
        TOK[tok * DMODEL + h * DH + c] = acc;
    }
}

// ---------------- host driver ----------------
static float* sym(const void* p) { return (float*)p; }

extern "C" void kernel_launch(void* const* d_in, const int* in_sizes, int n_in,
                              void* d_out, int out_size)
{
    const float* x      = (const float*)d_in[0];
    const float* ln_w   = (const float*)d_in[1];
    const float* ln_b   = (const float*)d_in[2];
    const float* w_qkv  = (const float*)d_in[3];
    const float* w_out  = (const float*)d_in[4];
    const float* b_out  = (const float*)d_in[5];
    const float* conv_w = (const float*)d_in[6];
    float* out = (float*)d_out;

    void *p_xn, *p_qkv, *p_q, *p_k, *p_v, *p_ql, *p_kl, *p_a1, *p_a3, *p_a2;
    void *p_za, *p_zb, *p_xz, *p_t1, *p_t2, *p_a3v, *p_o1, *p_oh, *p_tok, *p_s;
    cudaGetSymbolAddress(&p_xn, g_xn);   cudaGetSymbolAddress(&p_qkv, g_qkv);
    cudaGetSymbolAddress(&p_q, g_q);     cudaGetSymbolAddress(&p_k, g_k);
    cudaGetSymbolAddress(&p_v, g_v);     cudaGetSymbolAddress(&p_ql, g_ql);
    cudaGetSymbolAddress(&p_kl, g_kl);   cudaGetSymbolAddress(&p_a1, g_attn1);
    cudaGetSymbolAddress(&p_a3, g_attn3);cudaGetSymbolAddress(&p_a2, g_attn2);
    cudaGetSymbolAddress(&p_za, g_za);   cudaGetSymbolAddress(&p_zb, g_zb);
    cudaGetSymbolAddress(&p_xz, g_xz);   cudaGetSymbolAddress(&p_t1, g_t1);
    cudaGetSymbolAddress(&p_t2, g_t2);   cudaGetSymbolAddress(&p_a3v, g_a3v);
    cudaGetSymbolAddress(&p_o1, g_out1); cudaGetSymbolAddress(&p_oh, g_outh);
    cudaGetSymbolAddress(&p_tok, g_tok); cudaGetSymbolAddress(&p_s, g_scale);

    float *xn=(float*)p_xn, *qkv=(float*)p_qkv, *Q=(float*)p_q, *K=(float*)p_k, *V=(float*)p_v;
    float *QL=(float*)p_ql, *KL=(float*)p_kl, *A1=(float*)p_a1, *A3=(float*)p_a3, *A2=(float*)p_a2;
    float *ZA=(float*)p_za, *ZB=(float*)p_zb, *XZ=(float*)p_xz, *T1=(float*)p_t1, *T2=(float*)p_t2;
    float *A3V=(float*)p_a3v, *O1=(float*)p_o1, *OH=(float*)p_oh, *TOK=(float*)p_tok, *S=(float*)p_s;

    const long long sQ  = (long long)SEQ * DH;     // per-bh stride of q/k/v
    const long long sL  = (long long)LM * DH;      // per-bh stride of ql/kl
    const long long sA1 = (long long)SEQ * LM;     // attn1 / out1
    const long long sA2 = (long long)LM * LM;
    const long long sA3 = (long long)LM * SEQ;

    // 1. LayerNorm
    ln_kernel<<<NTOK, 128>>>(x, ln_w, ln_b, xn);
    // 2. qkv = xn @ w_qkv^T   [32768,1536]
    gemm_big<true><<<dim3(12, 256, 1), 256>>>(xn, w_qkv, qkv,
        NTOK, 3*DMODEL, DMODEL, 0, 0, 0, 1.f, nullptr, nullptr);
    // 3. split heads
    split_qkv<<<(NTOK * DMODEL) / 256, 256>>>(qkv, Q, K, V);
    // 4. landmarks
    landmark<<<(BH*LM*DH)/256, 256>>>(Q, QL);
    landmark<<<(BH*LM*DH)/256, 256>>>(K, KL);
    // 5. attn1 = softmax(Q @ KL^T)  [bh, 8192, 256]
    gemm_big<true><<<dim3(2, 64, BH), 256>>>(Q, KL, A1,
        SEQ, LM, DH, sQ, sL, sA1, 1.f, nullptr, nullptr);
    softmax_rows<1><<<BH*SEQ, 256>>>(A1);
    // 6. attn2 = softmax(QL @ KL^T) [bh, 256, 256]
    gemm_small<true><<<dim3(4, 4, BH), 256>>>(QL, KL, A2,
        LM, LM, DH, sL, sL, sA2, 1.f, 0.f);
    softmax_rows<1><<<BH*LM, 256>>>(A2);
    // 7. attn3 = softmax(QL @ K^T)  [bh, 256, 8192]
    gemm_big<true><<<dim3(64, 2, BH), 256>>>(QL, K, A3,
        LM, SEQ, DH, sL, sQ, sA3, 1.f, nullptr, nullptr);
    softmax_rows<32><<<BH*LM, 256>>>(A3);
    // 8. pinv scale + Z0
    scale_init<<<1, 1>>>(S);
    colrow_max<<<BH, 256>>>(A2, S);
    make_z0<<<(BH*LM*LM)/256, 256>>>(A2, S, ZA);
    // 9. Moore-Penrose iterations (6)
    float* Zin = ZA; float* Zout = ZB;
    for (int it = 0; it < 6; ++it) {
        gemm_small<false><<<dim3(4,4,BH), 256>>>(A2, Zin, XZ, LM, LM, LM, sA2, sA2, sA2, 1.f, 0.f);
        diag_sub<<<(BH*LM*LM)/256, 256>>>(XZ, T1, 7.f);
        gemm_small<false><<<dim3(4,4,BH), 256>>>(XZ, T1, T2, LM, LM, LM, sA2, sA2, sA2, -1.f, 15.f);
        gemm_small<false><<<dim3(4,4,BH), 256>>>(XZ, T2, T1, LM, LM, LM, sA2, sA2, sA2, -1.f, 13.f);
        gemm_small<false><<<dim3(4,4,BH), 256>>>(Zin, T1, Zout, LM, LM, LM, sA2, sA2, sA2, 0.25f, 0.f);
        float* tmp = Zin; Zin = Zout; Zout = tmp;
    }
    // Zin now holds Z (== ZA after 6 iters)
    // 10. a3v = attn3 @ V   [bh, 256, 64]
    gemm_small<false><<<dim3(1, 4, BH), 256>>>(A3, V, A3V,
        LM, DH, SEQ, sA3, sQ, sL, 1.f, 0.f);
    // 11. out1 = attn1 @ Z  [bh, 8192, 256]
    gemm_big<false><<<dim3(2, 64, BH), 256>>>(A1, Zin, O1,
        SEQ, LM, LM, sA1, sA2, sA1, 1.f, nullptr, nullptr);
    // 12. outh = out1 @ a3v [bh, 8192, 64]
    gemm_small<false><<<dim3(1, 128, BH), 256>>>(O1, A3V, OH,
        SEQ, DH, LM, sA1, sL, sQ, 1.f, 0.f);
    // 13. conv residual + combine -> token-major
    conv_combine<<<dim3(SEQ/64, BH), 256>>>(V, OH, conv_w, TOK);
    // 14. final: out = x + TOK @ w_out^T + b_out
    gemm_big<true><<<dim3(4, 256, 1), 256>>>(TOK, w_out, out,
        NTOK, DMODEL, DMODEL, 0, 0, 0, 1.f, b_out, x);
}

// round 2
// speedup vs baseline: 2.1376x; 2.1376x over previous
#include <cuda_runtime.h>
#include <cstdint>

// ---------------- problem constants ----------------
#define BATCH 4
#define SEQ   8192
#define DMODEL 512
#define HEADS 8
#define DH    64
#define LM    256
#define LGRP  32
#define NTOK  (BATCH*SEQ)
#define BH    (BATCH*HEADS)
#define KSZ   33

// ---------------- scratch ----------------
__device__ float g_xn   [(size_t)NTOK*DMODEL];
__device__ float g_qkv  [(size_t)NTOK*3*DMODEL];
__device__ float g_q    [(size_t)BH*SEQ*DH];
__device__ float g_k    [(size_t)BH*SEQ*DH];
__device__ float g_v    [(size_t)BH*SEQ*DH];
__device__ float g_ql   [(size_t)BH*LM*DH];
__device__ float g_kl   [(size_t)BH*LM*DH];
__device__ float g_attn1[(size_t)BH*SEQ*LM];
__device__ float g_attn3[(size_t)BH*LM*SEQ];
__device__ float g_attn2[(size_t)BH*LM*LM];
__device__ float g_za   [(size_t)BH*LM*LM];
__device__ float g_zb   [(size_t)BH*LM*LM];
__device__ float g_xz   [(size_t)BH*LM*LM];
__device__ float g_t1   [(size_t)BH*LM*LM];
__device__ float g_t2   [(size_t)BH*LM*LM];
__device__ float g_a3v  [(size_t)BH*LM*DH];
__device__ float g_za3v [(size_t)BH*LM*DH];
__device__ float g_outh [(size_t)BH*SEQ*DH];
__device__ float g_tok  [(size_t)NTOK*DMODEL];
__device__ float g_scale[2];

// ---------------- helpers ----------------
__device__ __forceinline__ unsigned f2tf(float f) {
    unsigned r;
    asm("cvt.rna.tf32.f32 %0, %1;" : "=r"(r) : "f"(f));
    return r;
}

__device__ __forceinline__ void mma_tf32(float* c, const unsigned* a, const unsigned* b) {
    asm volatile(
        "mma.sync.aligned.m16n8k8.row.col.f32.tf32.tf32.f32 "
        "{%0,%1,%2,%3},{%4,%5,%6,%7},{%8,%9},{%0,%1,%2,%3};"
        : "+f"(c[0]), "+f"(c[1]), "+f"(c[2]), "+f"(c[3])
        : "r"(a[0]), "r"(a[1]), "r"(a[2]), "r"(a[3]), "r"(b[0]), "r"(b[1]));
}

// ---------------- LayerNorm ----------------
__global__ void ln_kernel(const float* __restrict__ x, const float* __restrict__ w,
                          const float* __restrict__ b, float* __restrict__ y)
{
    int row = blockIdx.x;
    int tid = threadIdx.x;
    const float* xr = x + (long long)row * DMODEL;
    float4 v = *(const float4*)(xr + tid * 4);
    float s  = v.x + v.y + v.z + v.w;
    float s2 = v.x*v.x + v.y*v.y + v.z*v.z + v.w*v.w;
    __shared__ float r1[128], r2[128];
    r1[tid] = s; r2[tid] = s2; __syncthreads();
    for (int t = 64; t > 0; t >>= 1) {
        if (tid < t) { r1[tid] += r1[tid+t]; r2[tid] += r2[tid+t]; }
        __syncthreads();
    }
    float mean = r1[0] * (1.0f / DMODEL);
    float var  = r2[0] * (1.0f / DMODEL) - mean * mean;
    float inv  = rsqrtf(var + 1e-5f);
    float4 w4 = *(const float4*)(w + tid * 4);
    float4 b4 = *(const float4*)(b + tid * 4);
    float4 o;
    o.x = (v.x - mean) * inv * w4.x + b4.x;
    o.y = (v.y - mean) * inv * w4.y + b4.y;
    o.z = (v.z - mean) * inv * w4.z + b4.z;
    o.w = (v.w - mean) * inv * w4.w + b4.w;
    *(float4*)(y + (long long)row * DMODEL + tid * 4) = o;
}

// ---------------- tensor-core GEMM (tf32 mma.m16n8k8) ----------------
// C[M,N] = alpha * A[M,K] @ op(B) + betaI*I (+ bias) (+ resid)
// op(B) = B^T if TB (B stored [N,K]); else B stored [K,N].
// All of M,N multiples of BM,BN; K multiple of 16.
template<int BM, int BN, int WARPS_M, int WARPS_N, bool TB>
__global__ void __launch_bounds__(32*WARPS_M*WARPS_N) gemm_tc(
    const float* __restrict__ A, const float* __restrict__ B, float* __restrict__ C,
    int M, int N, int K, long long sA, long long sB, long long sC,
    float alpha, float betaI, const float* __restrict__ bias, const float* __restrict__ resid)
{
    constexpr int BK  = 16;
    constexpr int NTH = 32 * WARPS_M * WARPS_N;
    constexpr int WM  = BM / WARPS_M;
    constexpr int WN  = BN / WARPS_N;
    constexpr int MT  = WM / 16;
    constexpr int NT  = WN / 8;
    constexpr int AV  = BM * BK / 4 / NTH;   // float4 loads / thread for A tile
    constexpr int BV  = BN * BK / 4 / NTH;
    constexpr int BN4 = BN / 4;

    const int z = blockIdx.z;
    A += z * sA; B += z * sB; C += z * sC;
    if (resid) resid += z * sC;

    __shared__ unsigned As[BK][BM + 8];
    __shared__ unsigned Bs[BK][BN + 8];

    const int tid  = threadIdx.x;
    const int w    = tid >> 5, lane = tid & 31;
    const int g    = lane >> 2, t = lane & 3;
    const int wm   = (w / WARPS_N) * WM;
    const int wn   = (w % WARPS_N) * WN;
    const int m0   = blockIdx.y * BM;
    const int n0   = blockIdx.x * BN;

    float acc[MT][NT][4];
#pragma unroll
    for (int i = 0; i < MT; i++)
#pragma unroll
        for (int j = 0; j < NT; j++)
#pragma unroll
            for (int r = 0; r < 4; r++) acc[i][j][r] = 0.f;

    float4 pa[AV], pb[BV];

    auto load_regs = [&](int k0) {
#pragma unroll
        for (int it = 0; it < AV; ++it) {
            int idx = it * NTH + tid;
            int r = idx >> 2, kk = (idx & 3) << 2;
            pa[it] = *(const float4*)(A + (long long)(m0 + r) * K + k0 + kk);
        }
        if (TB) {
#pragma unroll
            for (int it = 0; it < BV; ++it) {
                int idx = it * NTH + tid;
                int r = idx >> 2, kk = (idx & 3) << 2;
                pb[it] = *(const float4*)(B + (long long)(n0 + r) * K + k0 + kk);
            }
        } else {
#pragma unroll
            for (int it = 0; it < BV; ++it) {
                int idx = it * NTH + tid;
                int kr = idx / BN4, c = (idx % BN4) << 2;
                pb[it] = *(const float4*)(B + (long long)(k0 + kr) * N + n0 + c);
            }
        }
    };

    auto store_smem = [&]() {
#pragma unroll
        for (int it = 0; it < AV; ++it) {
            int idx = it * NTH + tid;
            int r = idx >> 2, kk = (idx & 3) << 2;
            As[kk + 0][r] = f2tf(pa[it].x);
            As[kk + 1][r] = f2tf(pa[it].y);
            As[kk + 2][r] = f2tf(pa[it].z);
            As[kk + 3][r] = f2tf(pa[it].w);
        }
        if (TB) {
#pragma unroll
            for (int it = 0; it < BV; ++it) {
                int idx = it * NTH + tid;
                int r = idx >> 2, kk = (idx & 3) << 2;
                Bs[kk + 0][r] = f2tf(pb[it].x);
                Bs[kk + 1][r] = f2tf(pb[it].y);
                Bs[kk + 2][r] = f2tf(pb[it].z);
                Bs[kk + 3][r] = f2tf(pb[it].w);
            }
        } else {
#pragma unroll
            for (int it = 0; it < BV; ++it) {
                int idx = it * NTH + tid;
                int kr = idx / BN4, c = (idx % BN4) << 2;
                Bs[kr][c + 0] = f2tf(pb[it].x);
                Bs[kr][c + 1] = f2tf(pb[it].y);
                Bs[kr][c + 2] = f2tf(pb[it].z);
                Bs[kr][c + 3] = f2tf(pb[it].w);
            }
        }
    };

    const int nk = K / BK;
    load_regs(0);
    store_smem();
    __syncthreads();

    for (int kt = 0; kt < nk; ++kt) {
        if (kt + 1 < nk) load_regs((kt + 1) * BK);
#pragma unroll
        for (int ks = 0; ks < 2; ++ks) {
            const int kb = ks * 8;
            unsigned af[MT][4], bf[NT][2];
#pragma unroll
            for (int i = 0; i < MT; i++) {
                int mb = wm + i * 16 + g;
                af[i][0] = As[kb + t][mb];
                af[i][1] = As[kb + t][mb + 8];
                af[i][2] = As[kb + t + 4][mb];
                af[i][3] = As[kb + t + 4][mb + 8];
            }
#pragma unroll
            for (int j = 0; j < NT; j++) {
                int nb = wn + j * 8 + g;
                bf[j][0] = Bs[kb + t][nb];
                bf[j][1] = Bs[kb + t + 4][nb];
            }
#pragma unroll
            for (int i = 0; i < MT; i++)
#pragma unroll
                for (int j = 0; j < NT; j++)
                    mma_tf32(acc[i][j], af[i], bf[j]);
        }
        __syncthreads();
        if (kt + 1 < nk) {
            store_smem();
            __syncthreads();
        }
    }

    // epilogue
#pragma unroll
    for (int i = 0; i < MT; i++) {
        int gm = m0 + wm + i * 16 + g;
#pragma unroll
        for (int j = 0; j < NT; j++) {
            int gn = n0 + wn + j * 8 + 2 * t;
            float v00 = alpha * acc[i][j][0];
            float v01 = alpha * acc[i][j][1];
            float v10 = alpha * acc[i][j][2];
            float v11 = alpha * acc[i][j][3];
            if (bias) {
                v00 += bias[gn]; v01 += bias[gn + 1];
                v10 += bias[gn]; v11 += bias[gn + 1];
            }
            if (resid) {
                v00 += resid[(long long)gm * N + gn];
                v01 += resid[(long long)gm * N + gn + 1];
                v10 += resid[(long long)(gm + 8) * N + gn];
                v11 += resid[(long long)(gm + 8) * N + gn + 1];
            }
            if (betaI != 0.f) {
                if (gm == gn)         v00 += betaI;
                if (gm == gn + 1)     v01 += betaI;
                if (gm + 8 == gn)     v10 += betaI;
                if (gm + 8 == gn + 1) v11 += betaI;
            }
            *(float2*)(C + (long long)gm * N + gn)       = make_float2(v00, v01);
            *(float2*)(C + (long long)(gm + 8) * N + gn) = make_float2(v10, v11);
        }
    }
}

// ---------------- split qkv ----------------
__global__ void split_qkv(const float* __restrict__ QKV, float* __restrict__ Q,
                          float* __restrict__ K, float* __restrict__ V)
{
    long long idx = (long long)blockIdx.x * 256 + threadIdx.x;
    int c = idx & 63;
    int h = (int)((idx >> 6) & 7);
    long long tok = idx >> 9;
    int i = (int)(tok & (SEQ - 1));
    int b = (int)(tok >> 13);
    long long dst = (((long long)(b * HEADS + h) * SEQ) + i) * DH + c;
    long long src = tok * (3 * DMODEL) + h * DH + c;
    Q[dst] = QKV[src] * 0.125f;
    K[dst] = QKV[src + DMODEL];
    V[dst] = QKV[src + 2 * DMODEL];
}

// ---------------- landmark means ----------------
__global__ void landmark(const float* __restrict__ Q, float* __restrict__ QL)
{
    int idx = blockIdx.x * 256 + threadIdx.x;
    int c  = idx & 63;
    int m  = (idx >> 6) & 255;
    int bh = idx >> 14;
    const float* p = Q + ((long long)bh * SEQ + m * LGRP) * DH + c;
    float s = 0.f;
#pragma unroll
    for (int t = 0; t < LGRP; ++t) s += p[t * DH];
    QL[idx] = s * (1.f / LGRP);
}

// ---------------- row softmax ----------------
template<int E>
__global__ void softmax_rows(float* __restrict__ S)
{
    const int W = E * 256;
    float* row = S + (long long)blockIdx.x * W;
    int tid = threadIdx.x;
    float v[E];
    float mx = -1e30f;
#pragma unroll
    for (int i = 0; i < E; i++) { v[i] = row[tid + i * 256]; mx = fmaxf(mx, v[i]); }
    __shared__ float red[256];
    red[tid] = mx; __syncthreads();
    for (int t = 128; t > 0; t >>= 1) {
        if (tid < t) red[tid] = fmaxf(red[tid], red[tid + t]);
        __syncthreads();
    }
    mx = red[0]; __syncthreads();
    float sm = 0.f;
#pragma unroll
    for (int i = 0; i < E; i++) { v[i] = __expf(v[i] - mx); sm += v[i]; }
    red[tid] = sm; __syncthreads();
    for (int t = 128; t > 0; t >>= 1) {
        if (tid < t) red[tid] += red[tid + t];
        __syncthreads();
    }
    float inv = 1.f / red[0];
#pragma unroll
    for (int i = 0; i < E; i++) row[tid + i * 256] = v[i] * inv;
}

// ---------------- pinv scale ----------------
__global__ void scale_init(float* s) { s[0] = 0.f; s[1] = 0.f; }

__global__ void colrow_max(const float* __restrict__ A2, float* __restrict__ s)
{
    int bh = blockIdx.x, j = threadIdx.x;
    const float* X = A2 + (long long)bh * LM * LM;
    float cs = 0.f, rs = 0.f;
    for (int i = 0; i < LM; ++i) {
        cs += fabsf(X[i * LM + j]);
        rs += fabsf(X[j * LM + i]);
    }
    __shared__ float r1[256], r2[256];
    r1[j] = cs; r2[j] = rs; __syncthreads();
    for (int t = 128; t > 0; t >>= 1) {
        if (j < t) { r1[j] = fmaxf(r1[j], r1[j+t]); r2[j] = fmaxf(r2[j], r2[j+t]); }
        __syncthreads();
    }
    if (j == 0) {
        atomicMax((int*)&s[0], __float_as_int(r1[0]));
        atomicMax((int*)&s[1], __float_as_int(r2[0]));
    }
}

__global__ void make_z0(const float* __restrict__ A2, const float* __restrict__ s,
                        float* __restrict__ Z)
{
    long long idx = (long long)blockIdx.x * 256 + threadIdx.x;
    int c  = idx & 255;
    int r  = (int)((idx >> 8) & 255);
    int bh = (int)(idx >> 16);
    float inv = 1.f / (s[0] * s[1]);
    Z[idx] = A2[(long long)bh * LM * LM + (long long)c * LM + r] * inv;
}

__global__ void diag_sub(const float* __restrict__ XZ, float* __restrict__ T, float beta)
{
    long long idx = (long long)blockIdx.x * 256 + threadIdx.x;
    int c = idx & 255;
    int r = (int)((idx >> 8) & 255);
    T[idx] = (r == c ? beta : 0.f) - XZ[idx];
}

// ---------------- conv + combine ----------------
__global__ void __launch_bounds__(256) conv_combine(
    const float* __restrict__ V, const float* __restrict__ O,
    const float* __restrict__ cw, float* __restrict__ TOK)
{
    int bh = blockIdx.y;
    int h = bh & 7, b = bh >> 3;
    int i0 = blockIdx.x * 64;
    __shared__ float sv[96][64];
    __shared__ float w[KSZ];
    int tid = threadIdx.x;
    if (tid < KSZ) w[tid] = cw[h * KSZ + tid];
    const float* Vb = V + (long long)bh * SEQ * DH;
    for (int e = tid; e < 96 * 64; e += 256) {
        int rr = e >> 6, c = e & 63;
        int gi = i0 - 16 + rr;
        sv[rr][c] = (gi >= 0 && gi < SEQ) ? Vb[(long long)gi * DH + c] : 0.f;
    }
    __syncthreads();
    int c  = tid & 63;
    int ib = tid >> 6;
#pragma unroll 4
    for (int j = 0; j < 16; ++j) {
        int il = ib * 16 + j;
        float acc = O[((long long)bh * SEQ + i0 + il) * DH + c];
#pragma unroll
        for (int t = 0; t < KSZ; ++t) acc += w[t] * sv[il + t][c];
        long long tok = (long long)b * SEQ + i0 + il;
        TOK[tok * DMODEL + h * DH + c] = acc;
    }
}

// ---------------- host driver ----------------
extern "C" void kernel_launch(void* const* d_in, const int* in_sizes, int n_in,
                              void* d_out, int out_size)
{
    const float* x      = (const float*)d_in[0];
    const float* ln_w   = (const float*)d_in[1];
    const float* ln_b   = (const float*)d_in[2];
    const float* w_qkv  = (const float*)d_in[3];
    const float* w_out  = (const float*)d_in[4];
    const float* b_out  = (const float*)d_in[5];
    const float* conv_w = (const float*)d_in[6];
    float* out = (float*)d_out;

    void *p;
    cudaGetSymbolAddress(&p, g_xn);    float* xn  = (float*)p;
    cudaGetSymbolAddress(&p, g_qkv);   float* qkv = (float*)p;
    cudaGetSymbolAddress(&p, g_q);     float* Q   = (float*)p;
    cudaGetSymbolAddress(&p, g_k);     float* K   = (float*)p;
    cudaGetSymbolAddress(&p, g_v);     float* V   = (float*)p;
    cudaGetSymbolAddress(&p, g_ql);    float* QL  = (float*)p;
    cudaGetSymbolAddress(&p, g_kl);    float* KL  = (float*)p;
    cudaGetSymbolAddress(&p, g_attn1); float* A1  = (float*)p;
    cudaGetSymbolAddress(&p, g_attn3); float* A3  = (float*)p;
    cudaGetSymbolAddress(&p, g_attn2); float* A2  = (float*)p;
    cudaGetSymbolAddress(&p, g_za);    float* ZA  = (float*)p;
    cudaGetSymbolAddress(&p, g_zb);    float* ZB  = (float*)p;
    cudaGetSymbolAddress(&p, g_xz);    float* XZ  = (float*)p;
    cudaGetSymbolAddress(&p, g_t1);    float* T1  = (float*)p;
    cudaGetSymbolAddress(&p, g_t2);    float* T2  = (float*)p;
    cudaGetSymbolAddress(&p, g_a3v);   float* A3V = (float*)p;
    cudaGetSymbolAddress(&p, g_za3v);  float* ZAV = (float*)p;
    cudaGetSymbolAddress(&p, g_outh);  float* OH  = (float*)p;
    cudaGetSymbolAddress(&p, g_tok);   float* TOK = (float*)p;
    cudaGetSymbolAddress(&p, g_scale); float* S   = (float*)p;

    const long long sQ  = (long long)SEQ * DH;
    const long long sL  = (long long)LM * DH;
    const long long sA1 = (long long)SEQ * LM;
    const long long sA2 = (long long)LM * LM;
    const long long sA3 = (long long)LM * SEQ;

    // 1. LayerNorm
    ln_kernel<<<NTOK, 128>>>(x, ln_w, ln_b, xn);
    // 2. qkv = xn @ w_qkv^T  [32768,1536,512]
    gemm_tc<128,128,2,4,true><<<dim3(12, 256, 1), 256>>>(xn, w_qkv, qkv,
        NTOK, 3*DMODEL, DMODEL, 0, 0, 0, 1.f, 0.f, nullptr, nullptr);
    // 3. split heads
    split_qkv<<<(NTOK * DMODEL) / 256, 256>>>(qkv, Q, K, V);
    // 4. landmarks
    landmark<<<(BH*LM*DH)/256, 256>>>(Q, QL);
    landmark<<<(BH*LM*DH)/256, 256>>>(K, KL);
    // 5. attn1 = softmax(Q @ KL^T)  [bh,8192,256,64]
    gemm_tc<128,128,2,4,true><<<dim3(2, 64, BH), 256>>>(Q, KL, A1,
        SEQ, LM, DH, sQ, sL, sA1, 1.f, 0.f, nullptr, nullptr);
    softmax_rows<1><<<BH*SEQ, 256>>>(A1);
    // 6. attn2 = softmax(QL @ KL^T) [bh,256,256,64]
    gemm_tc<64,64,2,2,true><<<dim3(4, 4, BH), 128>>>(QL, KL, A2,
        LM, LM, DH, sL, sL, sA2, 1.f, 0.f, nullptr, nullptr);
    softmax_rows<1><<<BH*LM, 256>>>(A2);
    // 7. attn3 = softmax(QL @ K^T)  [bh,256,8192,64]
    gemm_tc<128,128,2,4,true><<<dim3(64, 2, BH), 256>>>(QL, K, A3,
        LM, SEQ, DH, sL, sQ, sA3, 1.f, 0.f, nullptr, nullptr);
    softmax_rows<32><<<BH*LM, 256>>>(A3);
    // 8. pinv init
    scale_init<<<1, 1>>>(S);
    colrow_max<<<BH, 256>>>(A2, S);
    make_z0<<<(BH*LM*LM)/256, 256>>>(A2, S, ZA);
    // 9. Moore-Penrose iterations
    float* Zin = ZA; float* Zout = ZB;
    for (int it = 0; it < 6; ++it) {
        gemm_tc<64,64,2,2,false><<<dim3(4,4,BH), 128>>>(A2, Zin, XZ,
            LM, LM, LM, sA2, sA2, sA2, 1.f, 0.f, nullptr, nullptr);
        diag_sub<<<(BH*LM*LM)/256, 256>>>(XZ, T1, 7.f);
        gemm_tc<64,64,2,2,false><<<dim3(4,4,BH), 128>>>(XZ, T1, T2,
            LM, LM, LM, sA2, sA2, sA2, -1.f, 15.f, nullptr, nullptr);
        gemm_tc<64,64,2,2,false><<<dim3(4,4,BH), 128>>>(XZ, T2, T1,
            LM, LM, LM, sA2, sA2, sA2, -1.f, 13.f, nullptr, nullptr);
        gemm_tc<64,64,2,2,false><<<dim3(4,4,BH), 128>>>(Zin, T1, Zout,
            LM, LM, LM, sA2, sA2, sA2, 0.25f, 0.f, nullptr, nullptr);
        float* tmp = Zin; Zin = Zout; Zout = tmp;
    }
    // 10. a3v = attn3 @ V   [bh,256,64,8192]
    gemm_tc<64,64,2,2,false><<<dim3(1, 4, BH), 128>>>(A3, V, A3V,
        LM, DH, SEQ, sA3, sQ, sL, 1.f, 0.f, nullptr, nullptr);
    // 11. za3v = Z @ a3v    [bh,256,64,256]   (associativity: attn1@(Z@a3v))
    gemm_tc<64,64,2,2,false><<<dim3(1, 4, BH), 128>>>(Zin, A3V, ZAV,
        LM, DH, LM, sA2, sL, sL, 1.f, 0.f, nullptr, nullptr);
    // 12. outh = attn1 @ za3v [bh,8192,64,256]
    gemm_tc<64,64,2,2,false><<<dim3(1, 128, BH), 128>>>(A1, ZAV, OH,
        SEQ, DH, LM, sA1, sL, sQ, 1.f, 0.f, nullptr, nullptr);
    // 13. conv residual + combine -> token-major
    conv_combine<<<dim3(SEQ/64, BH), 256>>>(V, OH, conv_w, TOK);
    // 14. final: out = x + TOK @ w_out^T + b_out
    gemm_tc<128,128,2,4,true><<<dim3(4, 256, 1), 256>>>(TOK, w_out, out,
        NTOK, DMODEL, DMODEL, 0, 0, 0, 1.f, 0.f, b_out, x);
}

// round 3
// speedup vs baseline: 2.9568x; 1.3833x over previous
#include <cuda_runtime.h>
#include <cstdint>

// ---------------- problem constants ----------------
#define BATCH 4
#define SEQ   8192
#define DMODEL 512
#define HEADS 8
#define DH    64
#define LM    256
#define LGRP  32
#define NTOK  (BATCH*SEQ)
#define BH    (BATCH*HEADS)
#define KSZ   33
#define NCHUNK 8

// ---------------- scratch ----------------
__device__ float g_xn   [(size_t)NTOK*DMODEL];
__device__ float g_q    [(size_t)BH*SEQ*DH];
__device__ float g_k    [(size_t)BH*SEQ*DH];
__device__ float g_v    [(size_t)BH*SEQ*DH];
__device__ float g_ql   [(size_t)BH*LM*DH];
__device__ float g_kl   [(size_t)BH*LM*DH];
__device__ float g_attn2[(size_t)BH*LM*LM];
__device__ float g_za   [(size_t)BH*LM*LM];
__device__ float g_zb   [(size_t)BH*LM*LM];
__device__ float g_xz   [(size_t)BH*LM*LM];
__device__ float g_t1   [(size_t)BH*LM*LM];
__device__ float g_t2   [(size_t)BH*LM*LM];
__device__ float g_a3v  [(size_t)BH*LM*DH];
__device__ float g_zav  [(size_t)BH*LM*DH];
__device__ float g_outh [(size_t)BH*SEQ*DH];
__device__ float g_tok  [(size_t)NTOK*DMODEL];
__device__ float g_pacc [(size_t)BH*NCHUNK*LM*DH];
__device__ float g_pmax [(size_t)BH*NCHUNK*LM];
__device__ float g_psum [(size_t)BH*NCHUNK*LM];
__device__ float g_scale[2];

// ---------------- helpers ----------------
__device__ __forceinline__ unsigned f2tf(float f) {
    unsigned r;
    asm("cvt.rna.tf32.f32 %0, %1;" : "=r"(r) : "f"(f));
    return r;
}

__device__ __forceinline__ void mma_tf32(float* c, const unsigned* a, const unsigned* b) {
    asm volatile(
        "mma.sync.aligned.m16n8k8.row.col.f32.tf32.tf32.f32 "
        "{%0,%1,%2,%3},{%4,%5,%6,%7},{%8,%9},{%0,%1,%2,%3};"
        : "+f"(c[0]), "+f"(c[1]), "+f"(c[2]), "+f"(c[3])
        : "r"(a[0]), "r"(a[1]), "r"(a[2]), "r"(a[3]), "r"(b[0]), "r"(b[1]));
}

// ---------------- LayerNorm ----------------
__global__ void ln_kernel(const float* __restrict__ x, const float* __restrict__ w,
                          const float* __restrict__ b, float* __restrict__ y)
{
    int row = blockIdx.x;
    int tid = threadIdx.x;
    const float* xr = x + (long long)row * DMODEL;
    float4 v = *(const float4*)(xr + tid * 4);
    float s  = v.x + v.y + v.z + v.w;
    float s2 = v.x*v.x + v.y*v.y + v.z*v.z + v.w*v.w;
    __shared__ float r1[128], r2[128];
    r1[tid] = s; r2[tid] = s2; __syncthreads();
    for (int t = 64; t > 0; t >>= 1) {
        if (tid < t) { r1[tid] += r1[tid+t]; r2[tid] += r2[tid+t]; }
        __syncthreads();
    }
    float mean = r1[0] * (1.0f / DMODEL);
    float var  = r2[0] * (1.0f / DMODEL) - mean * mean;
    float inv  = rsqrtf(var + 1e-5f);
    float4 w4 = *(const float4*)(w + tid * 4);
    float4 b4 = *(const float4*)(b + tid * 4);
    float4 o;
    o.x = (v.x - mean) * inv * w4.x + b4.x;
    o.y = (v.y - mean) * inv * w4.y + b4.y;
    o.z = (v.z - mean) * inv * w4.z + b4.z;
    o.w = (v.w - mean) * inv * w4.w + b4.w;
    *(float4*)(y + (long long)row * DMODEL + tid * 4) = o;
}

// ---------------- tensor-core GEMM (tf32 mma.m16n8k8) ----------------
// MODE 0: C = alpha*A@op(B) + betaI*I (+bias) (+resid)
// MODE 1: qkv split epilogue -> Qp,Kp,Vp head-major (Q scaled by 0.125)
// MODE 2: C = alpha*A@op(B); C2 = beta2*I - C
template<int BM, int BN, int WARPS_M, int WARPS_N, bool TB, int MODE>
__global__ void __launch_bounds__(32*WARPS_M*WARPS_N) gemm_tc(
    const float* __restrict__ A, const float* __restrict__ B, float* __restrict__ C,
    int M, int N, int K, long long sA, long long sB, long long sC,
    float alpha, float betaI, const float* __restrict__ bias, const float* __restrict__ resid,
    float* __restrict__ C2, float beta2,
    float* __restrict__ Qp, float* __restrict__ Kp, float* __restrict__ Vp)
{
    constexpr int BK  = 16;
    constexpr int NTH = 32 * WARPS_M * WARPS_N;
    constexpr int WM  = BM / WARPS_M;
    constexpr int WN  = BN / WARPS_N;
    constexpr int MT  = WM / 16;
    constexpr int NT  = WN / 8;
    constexpr int AV  = BM * BK / 4 / NTH;
    constexpr int BV  = BN * BK / 4 / NTH;
    constexpr int BN4 = BN / 4;

    const int z = blockIdx.z;
    A += z * sA; B += z * sB;
    if (C)  C  += z * sC;
    if (C2) C2 += z * sC;
    if (resid) resid += z * sC;

    __shared__ unsigned As[BK][BM + 8];
    __shared__ unsigned Bs[BK][BN + 8];

    const int tid  = threadIdx.x;
    const int w    = tid >> 5, lane = tid & 31;
    const int g    = lane >> 2, t = lane & 3;
    const int wm   = (w / WARPS_N) * WM;
    const int wn   = (w % WARPS_N) * WN;
    const int m0   = blockIdx.y * BM;
    const int n0   = blockIdx.x * BN;

    float acc[MT][NT][4];
#pragma unroll
    for (int i = 0; i < MT; i++)
#pragma unroll
        for (int j = 0; j < NT; j++)
#pragma unroll
            for (int r = 0; r < 4; r++) acc[i][j][r] = 0.f;

    float4 pa[AV], pb[BV];

    auto load_regs = [&](int k0) {
#pragma unroll
        for (int it = 0; it < AV; ++it) {
            int idx = it * NTH + tid;
            int r = idx >> 2, kk = (idx & 3) << 2;
            pa[it] = *(const float4*)(A + (long long)(m0 + r) * K + k0 + kk);
        }
        if (TB) {
#pragma unroll
            for (int it = 0; it < BV; ++it) {
                int idx = it * NTH + tid;
                int r = idx >> 2, kk = (idx & 3) << 2;
                pb[it] = *(const float4*)(B + (long long)(n0 + r) * K + k0 + kk);
            }
        } else {
#pragma unroll
            for (int it = 0; it < BV; ++it) {
                int idx = it * NTH + tid;
                int kr = idx / BN4, c = (idx % BN4) << 2;
                pb[it] = *(const float4*)(B + (long long)(k0 + kr) * N + n0 + c);
            }
        }
    };

    auto store_smem = [&]() {
#pragma unroll
        for (int it = 0; it < AV; ++it) {
            int idx = it * NTH + tid;
            int r = idx >> 2, kk = (idx & 3) << 2;
            As[kk + 0][r] = f2tf(pa[it].x);
            As[kk + 1][r] = f2tf(pa[it].y);
            As[kk + 2][r] = f2tf(pa[it].z);
            As[kk + 3][r] = f2tf(pa[it].w);
        }
        if (TB) {
#pragma unroll
            for (int it = 0; it < BV; ++it) {
                int idx = it * NTH + tid;
                int r = idx >> 2, kk = (idx & 3) << 2;
                Bs[kk + 0][r] = f2tf(pb[it].x);
                Bs[kk + 1][r] = f2tf(pb[it].y);
                Bs[kk + 2][r] = f2tf(pb[it].z);
                Bs[kk + 3][r] = f2tf(pb[it].w);
            }
        } else {
#pragma unroll
            for (int it = 0; it < BV; ++it) {
                int idx = it * NTH + tid;
                int kr = idx / BN4, c = (idx % BN4) << 2;
                Bs[kr][c + 0] = f2tf(pb[it].x);
                Bs[kr][c + 1] = f2tf(pb[it].y);
                Bs[kr][c + 2] = f2tf(pb[it].z);
                Bs[kr][c + 3] = f2tf(pb[it].w);
            }
        }
    };

    const int nk = K / BK;
    load_regs(0);
    store_smem();
    __syncthreads();

    for (int kt = 0; kt < nk; ++kt) {
        if (kt + 1 < nk) load_regs((kt + 1) * BK);
#pragma unroll
        for (int ks = 0; ks < 2; ++ks) {
            const int kb = ks * 8;
            unsigned af[MT][4], bf[NT][2];
#pragma unroll
            for (int i = 0; i < MT; i++) {
                int mb = wm + i * 16 + g;
                af[i][0] = As[kb + t][mb];
                af[i][1] = As[kb + t][mb + 8];
                af[i][2] = As[kb + t + 4][mb];
                af[i][3] = As[kb + t + 4][mb + 8];
            }
#pragma unroll
            for (int j = 0; j < NT; j++) {
                int nb = wn + j * 8 + g;
                bf[j][0] = Bs[kb + t][nb];
                bf[j][1] = Bs[kb + t + 4][nb];
            }
#pragma unroll
            for (int i = 0; i < MT; i++)
#pragma unroll
                for (int j = 0; j < NT; j++)
                    mma_tf32(acc[i][j], af[i], bf[j]);
        }
        __syncthreads();
        if (kt + 1 < nk) {
            store_smem();
            __syncthreads();
        }
    }

    // epilogue
#pragma unroll
    for (int i = 0; i < MT; i++) {
        int gm = m0 + wm + i * 16 + g;
#pragma unroll
        for (int j = 0; j < NT; j++) {
            int gn = n0 + wn + j * 8 + 2 * t;
            float v00 = alpha * acc[i][j][0];
            float v01 = alpha * acc[i][j][1];
            float v10 = alpha * acc[i][j][2];
            float v11 = alpha * acc[i][j][3];
            if (MODE == 1) {
                int which = gn >> 9;
                int h = (gn >> 6) & 7;
                int c = gn & 63;
                float sc = (which == 0) ? 0.125f : 1.f;
                float* tgt = (which == 0) ? Qp : ((which == 1) ? Kp : Vp);
                int b0i = gm >> 13, i0i = gm & (SEQ - 1);
                int b1i = (gm + 8) >> 13, i1i = (gm + 8) & (SEQ - 1);
                long long d0 = (((long long)(b0i * HEADS + h)) * SEQ + i0i) * DH + c;
                long long d1 = (((long long)(b1i * HEADS + h)) * SEQ + i1i) * DH + c;
                *(float2*)(tgt + d0) = make_float2(v00 * sc, v01 * sc);
                *(float2*)(tgt + d1) = make_float2(v10 * sc, v11 * sc);
            } else {
                if (bias) {
                    v00 += bias[gn]; v01 += bias[gn + 1];
                    v10 += bias[gn]; v11 += bias[gn + 1];
                }
                if (resid) {
                    v00 += resid[(long long)gm * N + gn];
                    v01 += resid[(long long)gm * N + gn + 1];
                    v10 += resid[(long long)(gm + 8) * N + gn];
                    v11 += resid[(long long)(gm + 8) * N + gn + 1];
                }
                if (betaI != 0.f) {
                    if (gm == gn)         v00 += betaI;
                    if (gm == gn + 1)     v01 += betaI;
                    if (gm + 8 == gn)     v10 += betaI;
                    if (gm + 8 == gn + 1) v11 += betaI;
                }
                *(float2*)(C + (long long)gm * N + gn)       = make_float2(v00, v01);
                *(float2*)(C + (long long)(gm + 8) * N + gn) = make_float2(v10, v11);
                if (MODE == 2) {
                    float w00 = ((gm == gn)         ? beta2 : 0.f) - v00;
                    float w01 = ((gm == gn + 1)     ? beta2 : 0.f) - v01;
                    float w10 = ((gm + 8 == gn)     ? beta2 : 0.f) - v10;
                    float w11 = ((gm + 8 == gn + 1) ? beta2 : 0.f) - v11;
                    *(float2*)(C2 + (long long)gm * N + gn)       = make_float2(w00, w01);
                    *(float2*)(C2 + (long long)(gm + 8) * N + gn) = make_float2(w10, w11);
                }
            }
        }
    }
}

// ---------------- fused softmax(A@B^T)@C kernel ----------------
// A: [bh][M_total][64] (queries), B: [bh][N_total][64] (keys), C: [bh][N_total][64] (values)
// FINAL: OUT[bh][M_total][64] = softmax_rows(A@B^T) @ C   (exact if chunk covers full N)
// PARTIAL: per-chunk online-softmax partials (acc,max,sum) for a later combine.
// Block: 64 query rows, 8 warps = 4 (m) x 2 (n). Inner n-tile = 64 keys.
template<bool FINAL>
__global__ void __launch_bounds__(256) fused_sav(
    const float* __restrict__ A, const float* __restrict__ B, const float* __restrict__ C,
    float* __restrict__ OUT, float* __restrict__ PMAX, float* __restrict__ PSUM,
    int M_total, int N_total, int chunk_len)
{
    __shared__ unsigned smem_raw[64*68 * 2];
    unsigned* As  = smem_raw;              // [64 k][68] holds A tile transposed
    unsigned* BVs = smem_raw + 64*68;      // [64][68] K tile (transposed) then V tile (direct)
    float* macc = (float*)smem_raw;        // merge: [64][64] (overlaps As, dead by then)
    float* wmax = (float*)(smem_raw + 4096);
    float* wsum = (float*)(smem_raw + 4224);

    const int bh = blockIdx.z, mt = blockIdx.x, ck = blockIdx.y;
    const int m0 = mt * 64;
    const int tid = threadIdx.x;
    const int w = tid >> 5, lane = tid & 31;
    const int g = lane >> 2, t = lane & 3;
    const int wm = (w >> 1) * 16;          // 4 m-warps
    const int wni = w & 1;                 // 2 n-warps
    const int wn = wni * 32;

    const float* Ap = A + ((long long)bh * M_total + m0) * DH;
    const float* Bb = B + (long long)bh * N_total * DH;
    const float* Cb = C + (long long)bh * N_total * DH;

    // load A tile 64x64 transposed
#pragma unroll
    for (int it = 0; it < 4; ++it) {
        int idx = it * 256 + tid;
        int r = idx >> 4, kk = (idx & 15) << 2;
        float4 v = *(const float4*)(Ap + r * DH + kk);
        As[(kk+0)*68 + r] = f2tf(v.x);
        As[(kk+1)*68 + r] = f2tf(v.y);
        As[(kk+2)*68 + r] = f2tf(v.z);
        As[(kk+3)*68 + r] = f2tf(v.w);
    }

    float acc2[8][4];
#pragma unroll
    for (int nt = 0; nt < 8; ++nt)
#pragma unroll
        for (int r = 0; r < 4; ++r) acc2[nt][r] = 0.f;
    float rmax0 = -1e30f, rmax1 = -1e30f, rsum0 = 0.f, rsum1 = 0.f;

    const int n_start = ck * chunk_len;
    const int srcA = (lane & ~3) | (t >> 1);
    const int srcB = srcA + 2;
    const bool hi = t & 1;

    for (int nb = 0; nb < chunk_len; nb += 64) {
        __syncthreads();
        // load K tile 64x64 transposed into BVs
        const float* Kp = Bb + (long long)(n_start + nb) * DH;
#pragma unroll
        for (int it = 0; it < 4; ++it) {
            int idx = it * 256 + tid;
            int r = idx >> 4, kk = (idx & 15) << 2;
            float4 v = *(const float4*)(Kp + r * DH + kk);
            BVs[(kk+0)*68 + r] = f2tf(v.x);
            BVs[(kk+1)*68 + r] = f2tf(v.y);
            BVs[(kk+2)*68 + r] = f2tf(v.z);
            BVs[(kk+3)*68 + r] = f2tf(v.w);
        }
        __syncthreads();
        // S = A @ K^T : warp tile 16 x 32
        float sacc[4][4];
#pragma unroll
        for (int j = 0; j < 4; ++j)
#pragma unroll
            for (int r = 0; r < 4; ++r) sacc[j][r] = 0.f;
#pragma unroll
        for (int kk0 = 0; kk0 < 8; ++kk0) {
            int kb = kk0 * 8;
            unsigned af[4];
            int mb = wm + g;
            af[0] = As[(kb+t)*68 + mb];
            af[1] = As[(kb+t)*68 + mb + 8];
            af[2] = As[(kb+t+4)*68 + mb];
            af[3] = As[(kb+t+4)*68 + mb + 8];
#pragma unroll
            for (int j = 0; j < 4; ++j) {
                int nbq = wn + j * 8 + g;
                unsigned bf[2];
                bf[0] = BVs[(kb+t)*68 + nbq];
                bf[1] = BVs[(kb+t+4)*68 + nbq];
                mma_tf32(sacc[j], af, bf);
            }
        }
        // online softmax stats (rows g and g+8 of warp strip)
        float tm0 = -1e30f, tm1 = -1e30f;
#pragma unroll
        for (int j = 0; j < 4; ++j) {
            tm0 = fmaxf(tm0, fmaxf(sacc[j][0], sacc[j][1]));
            tm1 = fmaxf(tm1, fmaxf(sacc[j][2], sacc[j][3]));
        }
        tm0 = fmaxf(tm0, __shfl_xor_sync(0xffffffffu, tm0, 1));
        tm0 = fmaxf(tm0, __shfl_xor_sync(0xffffffffu, tm0, 2));
        tm1 = fmaxf(tm1, __shfl_xor_sync(0xffffffffu, tm1, 1));
        tm1 = fmaxf(tm1, __shfl_xor_sync(0xffffffffu, tm1, 2));
        float nm0 = fmaxf(rmax0, tm0), nm1 = fmaxf(rmax1, tm1);
        float sc0 = __expf(rmax0 - nm0), sc1 = __expf(rmax1 - nm1);
        float ts0 = 0.f, ts1 = 0.f;
#pragma unroll
        for (int j = 0; j < 4; ++j) {
            sacc[j][0] = __expf(sacc[j][0] - nm0);
            sacc[j][1] = __expf(sacc[j][1] - nm0);
            sacc[j][2] = __expf(sacc[j][2] - nm1);
            sacc[j][3] = __expf(sacc[j][3] - nm1);
            ts0 += sacc[j][0] + sacc[j][1];
            ts1 += sacc[j][2] + sacc[j][3];
        }
        ts0 += __shfl_xor_sync(0xffffffffu, ts0, 1);
        ts0 += __shfl_xor_sync(0xffffffffu, ts0, 2);
        ts1 += __shfl_xor_sync(0xffffffffu, ts1, 1);
        ts1 += __shfl_xor_sync(0xffffffffu, ts1, 2);
        rsum0 = rsum0 * sc0 + ts0;
        rsum1 = rsum1 * sc1 + ts1;
        rmax0 = nm0; rmax1 = nm1;
#pragma unroll
        for (int nt = 0; nt < 8; ++nt) {
            acc2[nt][0] *= sc0; acc2[nt][1] *= sc0;
            acc2[nt][2] *= sc1; acc2[nt][3] *= sc1;
        }
        __syncthreads();
        // load V tile 64x64 (direct layout [k][d])
        const float* Vp = Cb + (long long)(n_start + nb) * DH;
#pragma unroll
        for (int it = 0; it < 4; ++it) {
            int idx = it * 256 + tid;
            int r = idx >> 4, c4 = (idx & 15) << 2;
            float4 v = *(const float4*)(Vp + r * DH + c4);
            BVs[r*68 + c4 + 0] = f2tf(v.x);
            BVs[r*68 + c4 + 1] = f2tf(v.y);
            BVs[r*68 + c4 + 2] = f2tf(v.z);
            BVs[r*68 + c4 + 3] = f2tf(v.w);
        }
        __syncthreads();
        // acc2 += P @ V : contraction over this warp's 32 key cols
#pragma unroll
        for (int j2 = 0; j2 < 4; ++j2) {
            unsigned p0 = f2tf(sacc[j2][0]), p1 = f2tf(sacc[j2][1]);
            unsigned p2 = f2tf(sacc[j2][2]), p3 = f2tf(sacc[j2][3]);
            unsigned a0a = __shfl_sync(0xffffffffu, p0, srcA);
            unsigned a0b = __shfl_sync(0xffffffffu, p1, srcA);
            unsigned a1a = __shfl_sync(0xffffffffu, p2, srcA);
            unsigned a1b = __shfl_sync(0xffffffffu, p3, srcA);
            unsigned a2a = __shfl_sync(0xffffffffu, p0, srcB);
            unsigned a2b = __shfl_sync(0xffffffffu, p1, srcB);
            unsigned a3a = __shfl_sync(0xffffffffu, p2, srcB);
            unsigned a3b = __shfl_sync(0xffffffffu, p3, srcB);
            unsigned af2[4];
            af2[0] = hi ? a0b : a0a;
            af2[1] = hi ? a1b : a1a;
            af2[2] = hi ? a2b : a2a;
            af2[3] = hi ? a3b : a3a;
            int kb = wn + j2 * 8;
#pragma unroll
            for (int nt = 0; nt < 8; ++nt) {
                unsigned bf[2];
                bf[0] = BVs[(kb + t)*68 + nt*8 + g];
                bf[1] = BVs[(kb + t + 4)*68 + nt*8 + g];
                mma_tf32(acc2[nt], af2, bf);
            }
        }
    }

    // merge the two n-warps of each m-strip
    __syncthreads();
    if (t == 0) {
        wmax[wni*64 + wm + g]     = rmax0;
        wmax[wni*64 + wm + 8 + g] = rmax1;
        wsum[wni*64 + wm + g]     = rsum0;
        wsum[wni*64 + wm + 8 + g] = rsum1;
    }
    __syncthreads();
    int other = wni ^ 1;
    float om0 = wmax[other*64 + wm + g],     os0 = wsum[other*64 + wm + g];
    float om1 = wmax[other*64 + wm + 8 + g], os1 = wsum[other*64 + wm + 8 + g];
    float gm0 = fmaxf(rmax0, om0), gm1 = fmaxf(rmax1, om1);
    float f0 = __expf(rmax0 - gm0), f1 = __expf(rmax1 - gm1);
    float gs0 = rsum0 * f0 + os0 * __expf(om0 - gm0);
    float gs1 = rsum1 * f1 + os1 * __expf(om1 - gm1);
#pragma unroll
    for (int nt = 0; nt < 8; ++nt) {
        acc2[nt][0] *= f0; acc2[nt][1] *= f0;
        acc2[nt][2] *= f1; acc2[nt][3] *= f1;
    }
    __syncthreads();
    if (wni == 1) {
#pragma unroll
        for (int nt = 0; nt < 8; ++nt) {
            *(float2*)&macc[(wm + g)*64 + nt*8 + 2*t]     = make_float2(acc2[nt][0], acc2[nt][1]);
            *(float2*)&macc[(wm + 8 + g)*64 + nt*8 + 2*t] = make_float2(acc2[nt][2], acc2[nt][3]);
        }
    }
    __syncthreads();
    if (wni == 0) {
        int row0 = m0 + wm + g, row1 = row0 + 8;
        if (FINAL) {
            float inv0 = 1.f / gs0, inv1 = 1.f / gs1;
            float* O = OUT + (long long)bh * M_total * DH;
#pragma unroll
            for (int nt = 0; nt < 8; ++nt) {
                int cc = nt*8 + 2*t;
                float2 m0v = *(float2*)&macc[(wm + g)*64 + cc];
                float2 m1v = *(float2*)&macc[(wm + 8 + g)*64 + cc];
                *(float2*)(O + (long long)row0 * DH + cc) =
                    make_float2((acc2[nt][0] + m0v.x) * inv0, (acc2[nt][1] + m0v.y) * inv0);
                *(float2*)(O + (long long)row1 * DH + cc) =
                    make_float2((acc2[nt][2] + m1v.x) * inv1, (acc2[nt][3] + m1v.y) * inv1);
            }
        } else {
            long long pb = ((long long)bh * NCHUNK + ck) * M_total;
            float* O = OUT + pb * DH;
#pragma unroll
            for (int nt = 0; nt < 8; ++nt) {
                int cc = nt*8 + 2*t;
                float2 m0v = *(float2*)&macc[(wm + g)*64 + cc];
                float2 m1v = *(float2*)&macc[(wm + 8 + g)*64 + cc];
                *(float2*)(O + (long long)row0 * DH + cc) =
                    make_float2(acc2[nt][0] + m0v.x, acc2[nt][1] + m0v.y);
                *(float2*)(O + (long long)row1 * DH + cc) =
                    make_float2(acc2[nt][2] + m1v.x, acc2[nt][3] + m1v.y);
            }
            if (t == 0) {
                PMAX[pb + row0] = gm0; PMAX[pb + row1] = gm1;
                PSUM[pb + row0] = gs0; PSUM[pb + row1] = gs1;
            }
        }
    }
}

// ---------------- combine chunk partials -> a3v ----------------
__global__ void sav_combine(const float* __restrict__ pacc, const float* __restrict__ pmax,
                            const float* __restrict__ psum, float* __restrict__ out)
{
    int idx = blockIdx.x * 256 + threadIdx.x;          // BH*LM*DH
    int d = idx & 63;
    int m = (idx >> 6) & (LM - 1);
    int bh = idx >> 14;
    float gmax = -1e30f;
#pragma unroll
    for (int ck = 0; ck < NCHUNK; ++ck)
        gmax = fmaxf(gmax, pmax[((long long)bh * NCHUNK + ck) * LM + m]);
    float gsum = 0.f, val = 0.f;
#pragma unroll
    for (int ck = 0; ck < NCHUNK; ++ck) {
        long long pb = ((long long)bh * NCHUNK + ck) * LM + m;
        float f = __expf(pmax[pb] - gmax);
        gsum += psum[pb] * f;
        val  += pacc[pb * DH + d] * f;
    }
    out[idx] = val / gsum;
}

// ---------------- landmark means ----------------
__global__ void landmark(const float* __restrict__ Q, float* __restrict__ QL)
{
    int idx = blockIdx.x * 256 + threadIdx.x;
    int c  = idx & 63;
    int m  = (idx >> 6) & 255;
    int bh = idx >> 14;
    const float* p = Q + ((long long)bh * SEQ + m * LGRP) * DH + c;
    float s = 0.f;
#pragma unroll
    for (int t = 0; t < LGRP; ++t) s += p[t * DH];
    QL[idx] = s * (1.f / LGRP);
}

// ---------------- row softmax (256-wide rows) ----------------
__global__ void softmax_rows(float* __restrict__ S)
{
    float* row = S + (long long)blockIdx.x * 256;
    int tid = threadIdx.x;
    float v = row[tid];
    __shared__ float red[256];
    red[tid] = v; __syncthreads();
    for (int t = 128; t > 0; t >>= 1) {
        if (tid < t) red[tid] = fmaxf(red[tid], red[tid + t]);
        __syncthreads();
    }
    float mx = red[0]; __syncthreads();
    v = __expf(v - mx);
    red[tid] = v; __syncthreads();
    for (int t = 128; t > 0; t >>= 1) {
        if (tid < t) red[tid] += red[tid + t];
        __syncthreads();
    }
    row[tid] = v / red[0];
}

// ---------------- pinv scale ----------------
__global__ void scale_init(float* s) { s[0] = 0.f; s[1] = 0.f; }

__global__ void colrow_max(const float* __restrict__ A2, float* __restrict__ s)
{
    int bh = blockIdx.x, j = threadIdx.x;
    const float* X = A2 + (long long)bh * LM * LM;
    float cs = 0.f, rs = 0.f;
    for (int i = 0; i < LM; ++i) {
        cs += fabsf(X[i * LM + j]);
        rs += fabsf(X[j * LM + i]);
    }
    __shared__ float r1[256], r2[256];
    r1[j] = cs; r2[j] = rs; __syncthreads();
    for (int t = 128; t > 0; t >>= 1) {
        if (j < t) { r1[j] = fmaxf(r1[j], r1[j+t]); r2[j] = fmaxf(r2[j], r2[j+t]); }
        __syncthreads();
    }
    if (j == 0) {
        atomicMax((int*)&s[0], __float_as_int(r1[0]));
        atomicMax((int*)&s[1], __float_as_int(r2[0]));
    }
}

__global__ void make_z0(const float* __restrict__ A2, const float* __restrict__ s,
                        float* __restrict__ Z)
{
    long long idx = (long long)blockIdx.x * 256 + threadIdx.x;
    int c  = idx & 255;
    int r  = (int)((idx >> 8) & 255);
    int bh = (int)(idx >> 16);
    float inv = 1.f / (s[0] * s[1]);
    Z[idx] = A2[(long long)bh * LM * LM + (long long)c * LM + r] * inv;
}

// ---------------- conv + combine ----------------
__global__ void __launch_bounds__(256) conv_combine(
    const float* __restrict__ V, const float* __restrict__ O,
    const float* __restrict__ cw, float* __restrict__ TOK)
{
    int bh = blockIdx.y;
    int h = bh & 7, b = bh >> 3;
    int i0 = blockIdx.x * 64;
    __shared__ float sv[96][64];
    __shared__ float w[KSZ];
    int tid = threadIdx.x;
    if (tid < KSZ) w[tid] = cw[h * KSZ + tid];
    const float* Vb = V + (long long)bh * SEQ * DH;
    for (int e = tid; e < 96 * 64; e += 256) {
        int rr = e >> 6, c = e & 63;
        int gi = i0 - 16 + rr;
        sv[rr][c] = (gi >= 0 && gi < SEQ) ? Vb[(long long)gi * DH + c] : 0.f;
    }
    __syncthreads();
    int c  = tid & 63;
    int ib = tid >> 6;
#pragma unroll 4
    for (int j = 0; j < 16; ++j) {
        int il = ib * 16 + j;
        float acc = O[((long long)bh * SEQ + i0 + il) * DH + c];
#pragma unroll
        for (int t = 0; t < KSZ; ++t) acc += w[t] * sv[il + t][c];
        long long tok = (long long)b * SEQ + i0 + il;
        TOK[tok * DMODEL + h * DH + c] = acc;
    }
}

// ---------------- host driver ----------------
extern "C" void kernel_launch(void* const* d_in, const int* in_sizes, int n_in,
                              void* d_out, int out_size)
{
    const float* x      = (const float*)d_in[0];
    const float* ln_w   = (const float*)d_in[1];
    const float* ln_b   = (const float*)d_in[2];
    const float* w_qkv  = (const float*)d_in[3];
    const float* w_out  = (const float*)d_in[4];
    const float* b_out  = (const float*)d_in[5];
    const float* conv_w = (const float*)d_in[6];
    float* out = (float*)d_out;

    void *p;
    cudaGetSymbolAddress(&p, g_xn);    float* xn  = (float*)p;
    cudaGetSymbolAddress(&p, g_q);     float* Q   = (float*)p;
    cudaGetSymbolAddress(&p, g_k);     float* K   = (float*)p;
    cudaGetSymbolAddress(&p, g_v);     float* V   = (float*)p;
    cudaGetSymbolAddress(&p, g_ql);    float* QL  = (float*)p;
    cudaGetSymbolAddress(&p, g_kl);    float* KL  = (float*)p;
    cudaGetSymbolAddress(&p, g_attn2); float* A2  = (float*)p;
    cudaGetSymbolAddress(&p, g_za);    float* ZA  = (float*)p;
    cudaGetSymbolAddress(&p, g_zb);    float* ZB  = (float*)p;
    cudaGetSymbolAddress(&p, g_xz);    float* XZ  = (float*)p;
    cudaGetSymbolAddress(&p, g_t1);    float* T1  = (float*)p;
    cudaGetSymbolAddress(&p, g_t2);    float* T2  = (float*)p;
    cudaGetSymbolAddress(&p, g_a3v);   float* A3V = (float*)p;
    cudaGetSymbolAddress(&p, g_zav);   float* ZAV = (float*)p;
    cudaGetSymbolAddress(&p, g_outh);  float* OH  = (float*)p;
    cudaGetSymbolAddress(&p, g_tok);   float* TOK = (float*)p;
    cudaGetSymbolAddress(&p, g_pacc);  float* PAC = (float*)p;
    cudaGetSymbolAddress(&p, g_pmax);  float* PMX = (float*)p;
    cudaGetSymbolAddress(&p, g_psum);  float* PSM = (float*)p;
    cudaGetSymbolAddress(&p, g_scale); float* S   = (float*)p;

    const long long sL  = (long long)LM * DH;
    const long long sA2 = (long long)LM * LM;

    // 1. LayerNorm
    ln_kernel<<<NTOK, 128>>>(x, ln_w, ln_b, xn);
    // 2. qkv GEMM with fused head-split epilogue (Q scaled)
    gemm_tc<128,128,2,4,true,1><<<dim3(12, 256, 1), 256>>>(xn, w_qkv, nullptr,
        NTOK, 3*DMODEL, DMODEL, 0, 0, 0, 1.f, 0.f, nullptr, nullptr, nullptr, 0.f, Q, K, V);
    // 3. landmarks
    landmark<<<(BH*LM*DH)/256, 256>>>(Q, QL);
    landmark<<<(BH*LM*DH)/256, 256>>>(K, KL);
    // 4. attn2 = softmax(QL @ KL^T)
    gemm_tc<64,64,2,2,true,0><<<dim3(4, 4, BH), 128>>>(QL, KL, A2,
        LM, LM, DH, sL, sL, sA2, 1.f, 0.f, nullptr, nullptr, nullptr, 0.f, nullptr, nullptr, nullptr);
    softmax_rows<<<BH*LM, 256>>>(A2);
    // 5. pinv init
    scale_init<<<1, 1>>>(S);
    colrow_max<<<BH, 256>>>(A2, S);
    make_z0<<<(BH*LM*LM)/256, 256>>>(A2, S, ZA);
    // 6. Moore-Penrose iterations (diag_sub fused into XZ gemm)
    float* Zin = ZA; float* Zout = ZB;
    for (int it = 0; it < 6; ++it) {
        gemm_tc<64,64,2,2,false,2><<<dim3(4,4,BH), 128>>>(A2, Zin, XZ,
            LM, LM, LM, sA2, sA2, sA2, 1.f, 0.f, nullptr, nullptr, T1, 7.f, nullptr, nullptr, nullptr);
        gemm_tc<64,64,2,2,false,0><<<dim3(4,4,BH), 128>>>(XZ, T1, T2,
            LM, LM, LM, sA2, sA2, sA2, -1.f, 15.f, nullptr, nullptr, nullptr, 0.f, nullptr, nullptr, nullptr);
        gemm_tc<64,64,2,2,false,0><<<dim3(4,4,BH), 128>>>(XZ, T2, T1,
            LM, LM, LM, sA2, sA2, sA2, -1.f, 13.f, nullptr, nullptr, nullptr, 0.f, nullptr, nullptr, nullptr);
        gemm_tc<64,64,2,2,false,0><<<dim3(4,4,BH), 128>>>(Zin, T1, Zout,
            LM, LM, LM, sA2, sA2, sA2, 0.25f, 0.f, nullptr, nullptr, nullptr, 0.f, nullptr, nullptr, nullptr);
        float* tmp = Zin; Zin = Zout; Zout = tmp;
    }
    // 7. a3v = softmax(QL @ K^T) @ V  (flash, chunked partials + combine)
    fused_sav<false><<<dim3(LM/64, NCHUNK, BH), 256>>>(QL, K, V,
        PAC, PMX, PSM, LM, SEQ, SEQ/NCHUNK);
    sav_combine<<<(BH*LM*DH)/256, 256>>>(PAC, PMX, PSM, A3V);
    // 8. ZAV = Z @ a3v
    gemm_tc<64,64,2,2,false,0><<<dim3(1, 4, BH), 128>>>(Zin, A3V, ZAV,
        LM, DH, LM, sA2, sL, sL, 1.f, 0.f, nullptr, nullptr, nullptr, 0.f, nullptr, nullptr, nullptr);
    // 9. outh = softmax(Q @ KL^T) @ ZAV (fused, exact)
    fused_sav<true><<<dim3(SEQ/64, 1, BH), 256>>>(Q, KL, ZAV,
        OH, nullptr, nullptr, SEQ, LM, LM);
    // 10. conv residual + combine -> token-major
    conv_combine<<<dim3(SEQ/64, BH), 256>>>(V, OH, conv_w, TOK);
    // 11. final: out = x + TOK @ w_out^T + b_out
    gemm_tc<128,128,2,4,true,0><<<dim3(4, 256, 1), 256>>>(TOK, w_out, out,
        NTOK, DMODEL, DMODEL, 0, 0, 0, 1.f, 0.f, b_out, x, nullptr, 0.f, nullptr, nullptr, nullptr);
}

// round 4
// speedup vs baseline: 4.2146x; 1.4254x over previous
#include <cuda_runtime.h>
#include <cstdint>

// ---------------- problem constants ----------------
#define BATCH 4
#define SEQ   8192
#define DMODEL 512
#define HEADS 8
#define DH    64
#define LM    256
#define LGRP  32
#define NTOK  (BATCH*SEQ)
#define BH    (BATCH*HEADS)
#define KSZ   33
#define NCHUNK 8

// ---------------- scratch ----------------
__device__ float g_xn   [(size_t)NTOK*DMODEL];
__device__ float g_q    [(size_t)BH*SEQ*DH];
__device__ float g_k    [(size_t)BH*SEQ*DH];
__device__ float g_v    [(size_t)BH*SEQ*DH];
__device__ float g_ql   [(size_t)BH*LM*DH];
__device__ float g_kl   [(size_t)BH*LM*DH];
__device__ float g_attn2[(size_t)BH*LM*LM];
__device__ float g_za   [(size_t)BH*LM*LM];
__device__ float g_zb   [(size_t)BH*LM*LM];
__device__ float g_xz   [(size_t)BH*LM*LM];
__device__ float g_t1   [(size_t)BH*LM*LM];
__device__ float g_t2   [(size_t)BH*LM*LM];
__device__ float g_a3v  [(size_t)BH*LM*DH];
__device__ float g_zav  [(size_t)BH*LM*DH];
__device__ float g_outh [(size_t)BH*SEQ*DH];
__device__ float g_tok  [(size_t)NTOK*DMODEL];
__device__ float g_pacc [(size_t)BH*NCHUNK*LM*DH];
__device__ float g_pmax [(size_t)BH*NCHUNK*LM];
__device__ float g_psum [(size_t)BH*NCHUNK*LM];
__device__ float g_scale[2];

// ---------------- helpers ----------------
__device__ __forceinline__ void mma_tf32(float* c, const unsigned* a, const unsigned* b) {
    asm volatile(
        "mma.sync.aligned.m16n8k8.row.col.f32.tf32.tf32.f32 "
        "{%0,%1,%2,%3},{%4,%5,%6,%7},{%8,%9},{%0,%1,%2,%3};"
        : "+f"(c[0]), "+f"(c[1]), "+f"(c[2]), "+f"(c[3])
        : "r"(a[0]), "r"(a[1]), "r"(a[2]), "r"(a[3]), "r"(b[0]), "r"(b[1]));
}

__device__ __forceinline__ void cpa16(float* s, const float* g) {
    unsigned sa = (unsigned)__cvta_generic_to_shared(s);
    asm volatile("cp.async.cg.shared.global [%0], [%1], 16;" :: "r"(sa), "l"(g));
}
#define CP_COMMIT() asm volatile("cp.async.commit_group;")
#define CP_WAIT1()  asm volatile("cp.async.wait_group 1;")
#define CP_WAIT0()  asm volatile("cp.async.wait_group 0;")

__device__ __forceinline__ unsigned fu(float f) { return __float_as_uint(f); }

// ---------------- LayerNorm ----------------
__global__ void ln_kernel(const float* __restrict__ x, const float* __restrict__ w,
                          const float* __restrict__ b, float* __restrict__ y)
{
    int row = blockIdx.x;
    int tid = threadIdx.x;
    const float* xr = x + (long long)row * DMODEL;
    float4 v = *(const float4*)(xr + tid * 4);
    float s  = v.x + v.y + v.z + v.w;
    float s2 = v.x*v.x + v.y*v.y + v.z*v.z + v.w*v.w;
    __shared__ float r1[128], r2[128];
    r1[tid] = s; r2[tid] = s2; __syncthreads();
    for (int t = 64; t > 0; t >>= 1) {
        if (tid < t) { r1[tid] += r1[tid+t]; r2[tid] += r2[tid+t]; }
        __syncthreads();
    }
    float mean = r1[0] * (1.0f / DMODEL);
    float var  = r2[0] * (1.0f / DMODEL) - mean * mean;
    float inv  = rsqrtf(var + 1e-5f);
    float4 w4 = *(const float4*)(w + tid * 4);
    float4 b4 = *(const float4*)(b + tid * 4);
    float4 o;
    o.x = (v.x - mean) * inv * w4.x + b4.x;
    o.y = (v.y - mean) * inv * w4.y + b4.y;
    o.z = (v.z - mean) * inv * w4.z + b4.z;
    o.w = (v.w - mean) * inv * w4.w + b4.w;
    *(float4*)(y + (long long)row * DMODEL + tid * 4) = o;
}

// ---------------- tensor-core GEMM, cp.async double-buffered ----------------
// MODE 0: C = alpha*A@op(B) + betaI*I (+bias) (+resid)
// MODE 1: qkv split epilogue -> Qp,Kp,Vp head-major (Q scaled by 0.125)
// MODE 2: C = alpha*A@op(B); C2 = beta2*I - C
template<int BM, int BN, int WARPS_M, int WARPS_N, bool TB, int MODE>
__global__ void __launch_bounds__(32*WARPS_M*WARPS_N) gemm_tc(
    const float* __restrict__ A, const float* __restrict__ B, float* __restrict__ C,
    int M, int N, int K, long long sA, long long sB, long long sC,
    float alpha, float betaI, const float* __restrict__ bias, const float* __restrict__ resid,
    float* __restrict__ C2, float beta2,
    float* __restrict__ Qp, float* __restrict__ Kp, float* __restrict__ Vp)
{
    constexpr int BK  = 16;
    constexpr int NTH = 32 * WARPS_M * WARPS_N;
    constexpr int WM  = BM / WARPS_M;
    constexpr int WN  = BN / WARPS_N;
    constexpr int MT  = WM / 16;
    constexpr int NT  = WN / 8;
    constexpr int SA  = BM * 20;                       // A stage: [BM][20]
    constexpr int SB  = TB ? BN * 20 : BK * (BN + 8);  // B stage
    constexpr int AC  = BM * 4 / NTH;                  // cp chunks per thread
    constexpr int BC  = TB ? BN * 4 / NTH : (BK * BN / 4) / NTH;

    const int z = blockIdx.z;
    A += z * sA; B += z * sB;
    if (C)  C  += z * sC;
    if (C2) C2 += z * sC;
    if (resid) resid += z * sC;

    __shared__ float smem[2 * (SA + SB)];

    const int tid  = threadIdx.x;
    const int w    = tid >> 5, lane = tid & 31;
    const int g    = lane >> 2, t = lane & 3;
    const int wm   = (w / WARPS_N) * WM;
    const int wn   = (w % WARPS_N) * WN;
    const int m0   = blockIdx.y * BM;
    const int n0   = blockIdx.x * BN;

    float acc[MT][NT][4];
#pragma unroll
    for (int i = 0; i < MT; i++)
#pragma unroll
        for (int j = 0; j < NT; j++)
#pragma unroll
            for (int r = 0; r < 4; r++) acc[i][j][r] = 0.f;

    auto load_stage = [&](int st, int k0) {
        float* as = smem + st * (SA + SB);
        float* bs = as + SA;
#pragma unroll
        for (int it = 0; it < AC; ++it) {
            int idx = it * NTH + tid;
            int r = idx >> 2, ch = (idx & 3) << 2;
            cpa16(as + r * 20 + ch, A + (long long)(m0 + r) * K + k0 + ch);
        }
        if (TB) {
#pragma unroll
            for (int it = 0; it < BC; ++it) {
                int idx = it * NTH + tid;
                int r = idx >> 2, ch = (idx & 3) << 2;
                cpa16(bs + r * 20 + ch, B + (long long)(n0 + r) * K + k0 + ch);
            }
        } else {
#pragma unroll
            for (int it = 0; it < BC; ++it) {
                int idx = it * NTH + tid;
                int kr = idx / (BN / 4), c = (idx % (BN / 4)) << 2;
                cpa16(bs + kr * (BN + 8) + c, B + (long long)(k0 + kr) * N + n0 + c);
            }
        }
    };

    const int nk = K / BK;
    load_stage(0, 0);
    CP_COMMIT();

    for (int kt = 0; kt < nk; ++kt) {
        if (kt + 1 < nk) {
            load_stage((kt + 1) & 1, (kt + 1) * BK);
            CP_COMMIT();
            CP_WAIT1();
        } else {
            CP_WAIT0();
        }
        __syncthreads();
        const float* as = smem + (kt & 1) * (SA + SB);
        const float* bs = as + SA;
#pragma unroll
        for (int ks = 0; ks < 2; ++ks) {
            const int kb = ks * 8;
            unsigned af[MT][4], bf[NT][2];
#pragma unroll
            for (int i = 0; i < MT; i++) {
                int mb = wm + i * 16;
                af[i][0] = fu(as[(mb + g) * 20 + kb + t]);
                af[i][1] = fu(as[(mb + 8 + g) * 20 + kb + t]);
                af[i][2] = fu(as[(mb + g) * 20 + kb + t + 4]);
                af[i][3] = fu(as[(mb + 8 + g) * 20 + kb + t + 4]);
            }
#pragma unroll
            for (int j = 0; j < NT; j++) {
                int nb = wn + j * 8 + g;
                if (TB) {
                    bf[j][0] = fu(bs[nb * 20 + kb + t]);
                    bf[j][1] = fu(bs[nb * 20 + kb + t + 4]);
                } else {
                    bf[j][0] = fu(bs[(kb + t) * (BN + 8) + nb]);
                    bf[j][1] = fu(bs[(kb + t + 4) * (BN + 8) + nb]);
                }
            }
#pragma unroll
            for (int i = 0; i < MT; i++)
#pragma unroll
                for (int j = 0; j < NT; j++)
                    mma_tf32(acc[i][j], af[i], bf[j]);
        }
        __syncthreads();
    }

    // epilogue
#pragma unroll
    for (int i = 0; i < MT; i++) {
        int gm = m0 + wm + i * 16 + g;
#pragma unroll
        for (int j = 0; j < NT; j++) {
            int gn = n0 + wn + j * 8 + 2 * t;
            float v00 = alpha * acc[i][j][0];
            float v01 = alpha * acc[i][j][1];
            float v10 = alpha * acc[i][j][2];
            float v11 = alpha * acc[i][j][3];
            if (MODE == 1) {
                int which = gn >> 9;
                int h = (gn >> 6) & 7;
                int c = gn & 63;
                float sc = (which == 0) ? 0.125f : 1.f;
                float* tgt = (which == 0) ? Qp : ((which == 1) ? Kp : Vp);
                int b0i = gm >> 13, i0i = gm & (SEQ - 1);
                int b1i = (gm + 8) >> 13, i1i = (gm + 8) & (SEQ - 1);
                long long d0 = (((long long)(b0i * HEADS + h)) * SEQ + i0i) * DH + c;
                long long d1 = (((long long)(b1i * HEADS + h)) * SEQ + i1i) * DH + c;
                *(float2*)(tgt + d0) = make_float2(v00 * sc, v01 * sc);
                *(float2*)(tgt + d1) = make_float2(v10 * sc, v11 * sc);
            } else {
                if (bias) {
                    v00 += bias[gn]; v01 += bias[gn + 1];
                    v10 += bias[gn]; v11 += bias[gn + 1];
                }
                if (resid) {
                    v00 += resid[(long long)gm * N + gn];
                    v01 += resid[(long long)gm * N + gn + 1];
                    v10 += resid[(long long)(gm + 8) * N + gn];
                    v11 += resid[(long long)(gm + 8) * N + gn + 1];
                }
                if (betaI != 0.f) {
                    if (gm == gn)         v00 += betaI;
                    if (gm == gn + 1)     v01 += betaI;
                    if (gm + 8 == gn)     v10 += betaI;
                    if (gm + 8 == gn + 1) v11 += betaI;
                }
                *(float2*)(C + (long long)gm * N + gn)       = make_float2(v00, v01);
                *(float2*)(C + (long long)(gm + 8) * N + gn) = make_float2(v10, v11);
                if (MODE == 2) {
                    float w00 = ((gm == gn)         ? beta2 : 0.f) - v00;
                    float w01 = ((gm == gn + 1)     ? beta2 : 0.f) - v01;
                    float w10 = ((gm + 8 == gn)     ? beta2 : 0.f) - v10;
                    float w11 = ((gm + 8 == gn + 1) ? beta2 : 0.f) - v11;
                    *(float2*)(C2 + (long long)gm * N + gn)       = make_float2(w00, w01);
                    *(float2*)(C2 + (long long)(gm + 8) * N + gn) = make_float2(w10, w11);
                }
            }
        }
    }
}

// ---------------- fused softmax(A@B^T)@C, cp.async double-buffered ----------
// Dynamic smem layout (floats):
//   Qs [64][68]      (reused post-loop: macc[64][64], wmax[128], wsum[128])
//   Ks 2 x [64][68]
//   Vs 2 x [64][72]
#define SAV_SMEM_FLOATS (64*68 + 2*64*68 + 2*64*72)
template<bool FINAL>
__global__ void __launch_bounds__(256) fused_sav(
    const float* __restrict__ A, const float* __restrict__ B, const float* __restrict__ C,
    float* __restrict__ OUT, float* __restrict__ PMAX, float* __restrict__ PSUM,
    int M_total, int N_total, int chunk_len)
{
    extern __shared__ float fs[];
    float* Qs = fs;
    float* Ks = fs + 64*68;
    float* Vs = Ks + 2*64*68;
    float* macc = Qs;
    float* wmax = Qs + 64*64;
    float* wsum = Qs + 64*64 + 128;

    const int bh = blockIdx.z, mt = blockIdx.x, ck = blockIdx.y;
    const int m0 = mt * 64;
    const int tid = threadIdx.x;
    const int w = tid >> 5, lane = tid & 31;
    const int g = lane >> 2, t = lane & 3;
    const int wm = (w >> 1) * 16;
    const int wni = w & 1;
    const int wn = wni * 32;

    const float* Ap = A + ((long long)bh * M_total + m0) * DH;
    const float* Bb = B + (long long)bh * N_total * DH;
    const float* Cb = C + (long long)bh * N_total * DH;

    // Q tile 64x64 row-major
#pragma unroll
    for (int it = 0; it < 4; ++it) {
        int idx = it * 256 + tid;
        int r = idx >> 4, c = (idx & 15) << 2;
        *(float4*)(Qs + r * 68 + c) = *(const float4*)(Ap + r * DH + c);
    }

    const int n_start = ck * chunk_len;

    auto load_kv = [&](int st, int nb) {
        const float* Kp = Bb + (long long)(n_start + nb) * DH;
        const float* Vp = Cb + (long long)(n_start + nb) * DH;
        float* ks = Ks + st * 64 * 68;
        float* vs = Vs + st * 64 * 72;
#pragma unroll
        for (int it = 0; it < 4; ++it) {
            int idx = it * 256 + tid;
            int r = idx >> 4, c = (idx & 15) << 2;
            cpa16(ks + r * 68 + c, Kp + r * DH + c);
        }
#pragma unroll
        for (int it = 0; it < 4; ++it) {
            int idx = it * 256 + tid;
            int r = idx >> 4, c = (idx & 15) << 2;
            cpa16(vs + r * 72 + c, Vp + r * DH + c);
        }
    };

    float acc2[8][4];
#pragma unroll
    for (int nt = 0; nt < 8; ++nt)
#pragma unroll
        for (int r = 0; r < 4; ++r) acc2[nt][r] = 0.f;
    float rmax0 = -1e30f, rmax1 = -1e30f, rsum0 = 0.f, rsum1 = 0.f;

    const int srcA = (lane & ~3) | (t >> 1);
    const int srcB = srcA + 2;
    const bool hi = t & 1;

    load_kv(0, 0);
    CP_COMMIT();

    const int nt_iters = chunk_len / 64;
    for (int itn = 0; itn < nt_iters; ++itn) {
        if (itn + 1 < nt_iters) {
            load_kv((itn + 1) & 1, (itn + 1) * 64);
            CP_COMMIT();
            CP_WAIT1();
        } else {
            CP_WAIT0();
        }
        __syncthreads();
        const float* ks = Ks + (itn & 1) * 64 * 68;
        const float* vs = Vs + (itn & 1) * 64 * 72;

        // S = Q @ K^T : warp tile 16 x 32
        float sacc[4][4];
#pragma unroll
        for (int j = 0; j < 4; ++j)
#pragma unroll
            for (int r = 0; r < 4; ++r) sacc[j][r] = 0.f;
#pragma unroll
        for (int kk0 = 0; kk0 < 8; ++kk0) {
            int kb = kk0 * 8;
            unsigned af[4];
            af[0] = fu(Qs[(wm + g) * 68 + kb + t]);
            af[1] = fu(Qs[(wm + 8 + g) * 68 + kb + t]);
            af[2] = fu(Qs[(wm + g) * 68 + kb + t + 4]);
            af[3] = fu(Qs[(wm + 8 + g) * 68 + kb + t + 4]);
#pragma unroll
            for (int j = 0; j < 4; ++j) {
                int nbq = wn + j * 8 + g;
                unsigned bf[2];
                bf[0] = fu(ks[nbq * 68 + kb + t]);
                bf[1] = fu(ks[nbq * 68 + kb + t + 4]);
                mma_tf32(sacc[j], af, bf);
            }
        }
        // online softmax
        float tm0 = -1e30f, tm1 = -1e30f;
#pragma unroll
        for (int j = 0; j < 4; ++j) {
            tm0 = fmaxf(tm0, fmaxf(sacc[j][0], sacc[j][1]));
            tm1 = fmaxf(tm1, fmaxf(sacc[j][2], sacc[j][3]));
        }
        tm0 = fmaxf(tm0, __shfl_xor_sync(0xffffffffu, tm0, 1));
        tm0 = fmaxf(tm0, __shfl_xor_sync(0xffffffffu, tm0, 2));
        tm1 = fmaxf(tm1, __shfl_xor_sync(0xffffffffu, tm1, 1));
        tm1 = fmaxf(tm1, __shfl_xor_sync(0xffffffffu, tm1, 2));
        float nm0 = fmaxf(rmax0, tm0), nm1 = fmaxf(rmax1, tm1);
        float sc0 = __expf(rmax0 - nm0), sc1 = __expf(rmax1 - nm1);
        float ts0 = 0.f, ts1 = 0.f;
#pragma unroll
        for (int j = 0; j < 4; ++j) {
            sacc[j][0] = __expf(sacc[j][0] - nm0);
            sacc[j][1] = __expf(sacc[j][1] - nm0);
            sacc[j][2] = __expf(sacc[j][2] - nm1);
            sacc[j][3] = __expf(sacc[j][3] - nm1);
            ts0 += sacc[j][0] + sacc[j][1];
            ts1 += sacc[j][2] + sacc[j][3];
        }
        ts0 += __shfl_xor_sync(0xffffffffu, ts0, 1);
        ts0 += __shfl_xor_sync(0xffffffffu, ts0, 2);
        ts1 += __shfl_xor_sync(0xffffffffu, ts1, 1);
        ts1 += __shfl_xor_sync(0xffffffffu, ts1, 2);
        rsum0 = rsum0 * sc0 + ts0;
        rsum1 = rsum1 * sc1 + ts1;
        rmax0 = nm0; rmax1 = nm1;
#pragma unroll
        for (int nt = 0; nt < 8; ++nt) {
            acc2[nt][0] *= sc0; acc2[nt][1] *= sc0;
            acc2[nt][2] *= sc1; acc2[nt][3] *= sc1;
        }
        // acc2 += P @ V
#pragma unroll
        for (int j2 = 0; j2 < 4; ++j2) {
            unsigned p0 = fu(sacc[j2][0]), p1 = fu(sacc[j2][1]);
            unsigned p2 = fu(sacc[j2][2]), p3 = fu(sacc[j2][3]);
            unsigned a0a = __shfl_sync(0xffffffffu, p0, srcA);
            unsigned a0b = __shfl_sync(0xffffffffu, p1, srcA);
            unsigned a1a = __shfl_sync(0xffffffffu, p2, srcA);
            unsigned a1b = __shfl_sync(0xffffffffu, p3, srcA);
            unsigned a2a = __shfl_sync(0xffffffffu, p0, srcB);
            unsigned a2b = __shfl_sync(0xffffffffu, p1, srcB);
            unsigned a3a = __shfl_sync(0xffffffffu, p2, srcB);
            unsigned a3b = __shfl_sync(0xffffffffu, p3, srcB);
            unsigned af2[4];
            af2[0] = hi ? a0b : a0a;
            af2[1] = hi ? a1b : a1a;
            af2[2] = hi ? a2b : a2a;
            af2[3] = hi ? a3b : a3a;
            int kb = wn + j2 * 8;
#pragma unroll
            for (int nt = 0; nt < 8; ++nt) {
                unsigned bf[2];
                bf[0] = fu(vs[(kb + t) * 72 + nt * 8 + g]);
                bf[1] = fu(vs[(kb + t + 4) * 72 + nt * 8 + g]);
                mma_tf32(acc2[nt], af2, bf);
            }
        }
        __syncthreads();
    }

    // merge the two n-warps
    if (t == 0) {
        wmax[wni*64 + wm + g]     = rmax0;
        wmax[wni*64 + wm + 8 + g] = rmax1;
        wsum[wni*64 + wm + g]     = rsum0;
        wsum[wni*64 + wm + 8 + g] = rsum1;
    }
    __syncthreads();
    int other = wni ^ 1;
    float om0 = wmax[other*64 + wm + g],     os0 = wsum[other*64 + wm + g];
    float om1 = wmax[other*64 + wm + 8 + g], os1 = wsum[other*64 + wm + 8 + g];
    float gm0 = fmaxf(rmax0, om0), gm1 = fmaxf(rmax1, om1);
    float f0 = __expf(rmax0 - gm0), f1 = __expf(rmax1 - gm1);
    float gs0 = rsum0 * f0 + os0 * __expf(om0 - gm0);
    float gs1 = rsum1 * f1 + os1 * __expf(om1 - gm1);
#pragma unroll
    for (int nt = 0; nt < 8; ++nt) {
        acc2[nt][0] *= f0; acc2[nt][1] *= f0;
        acc2[nt][2] *= f1; acc2[nt][3] *= f1;
    }
    __syncthreads();
    if (wni == 1) {
#pragma unroll
        for (int nt = 0; nt < 8; ++nt) {
            *(float2*)&macc[(wm + g)*64 + nt*8 + 2*t]     = make_float2(acc2[nt][0], acc2[nt][1]);
            *(float2*)&macc[(wm + 8 + g)*64 + nt*8 + 2*t] = make_float2(acc2[nt][2], acc2[nt][3]);
        }
    }
    __syncthreads();
    if (wni == 0) {
        int row0 = m0 + wm + g, row1 = row0 + 8;
        if (FINAL) {
            float inv0 = 1.f / gs0, inv1 = 1.f / gs1;
            float* O = OUT + (long long)bh * M_total * DH;
#pragma unroll
            for (int nt = 0; nt < 8; ++nt) {
                int cc = nt*8 + 2*t;
                float2 m0v = *(float2*)&macc[(wm + g)*64 + cc];
                float2 m1v = *(float2*)&macc[(wm + 8 + g)*64 + cc];
                *(float2*)(O + (long long)row0 * DH + cc) =
                    make_float2((acc2[nt][0] + m0v.x) * inv0, (acc2[nt][1] + m0v.y) * inv0);
                *(float2*)(O + (long long)row1 * DH + cc) =
                    make_float2((acc2[nt][2] + m1v.x) * inv1, (acc2[nt][3] + m1v.y) * inv1);
            }
        } else {
            long long pb = ((long long)bh * NCHUNK + ck) * M_total;
            float* O = OUT + pb * DH;
#pragma unroll
            for (int nt = 0; nt < 8; ++nt) {
                int cc = nt*8 + 2*t;
                float2 m0v = *(float2*)&macc[(wm + g)*64 + cc];
                float2 m1v = *(float2*)&macc[(wm + 8 + g)*64 + cc];
                *(float2*)(O + (long long)row0 * DH + cc) =
                    make_float2(acc2[nt][0] + m0v.x, acc2[nt][1] + m0v.y);
                *(float2*)(O + (long long)row1 * DH + cc) =
                    make_float2(acc2[nt][2] + m1v.x, acc2[nt][3] + m1v.y);
            }
            if (t == 0) {
                PMAX[pb + row0] = gm0; PMAX[pb + row1] = gm1;
                PSUM[pb + row0] = gs0; PSUM[pb + row1] = gs1;
            }
        }
    }
}

// ---------------- combine chunk partials -> a3v ----------------
__global__ void sav_combine(const float* __restrict__ pacc, const float* __restrict__ pmax,
                            const float* __restrict__ psum, float* __restrict__ out)
{
    int idx = blockIdx.x * 256 + threadIdx.x;
    int d = idx & 63;
    int m = (idx >> 6) & (LM - 1);
    int bh = idx >> 14;
    float gmax = -1e30f;
#pragma unroll
    for (int ck = 0; ck < NCHUNK; ++ck)
        gmax = fmaxf(gmax, pmax[((long long)bh * NCHUNK + ck) * LM + m]);
    float gsum = 0.f, val = 0.f;
#pragma unroll
    for (int ck = 0; ck < NCHUNK; ++ck) {
        long long pb = ((long long)bh * NCHUNK + ck) * LM + m;
        float f = __expf(pmax[pb] - gmax);
        gsum += psum[pb] * f;
        val  += pacc[pb * DH + d] * f;
    }
    out[idx] = val / gsum;
}

// ---------------- landmark means ----------------
__global__ void landmark(const float* __restrict__ Q, float* __restrict__ QL)
{
    int idx = blockIdx.x * 256 + threadIdx.x;
    int c  = idx & 63;
    int m  = (idx >> 6) & 255;
    int bh = idx >> 14;
    const float* p = Q + ((long long)bh * SEQ + m * LGRP) * DH + c;
    float s = 0.f;
#pragma unroll
    for (int t = 0; t < LGRP; ++t) s += p[t * DH];
    QL[idx] = s * (1.f / LGRP);
}

// ---------------- row softmax (256-wide rows) ----------------
__global__ void softmax_rows(float* __restrict__ S)
{
    float* row = S + (long long)blockIdx.x * 256;
    int tid = threadIdx.x;
    float v = row[tid];
    __shared__ float red[256];
    red[tid] = v; __syncthreads();
    for (int t = 128; t > 0; t >>= 1) {
        if (tid < t) red[tid] = fmaxf(red[tid], red[tid + t]);
        __syncthreads();
    }
    float mx = red[0]; __syncthreads();
    v = __expf(v - mx);
    red[tid] = v; __syncthreads();
    for (int t = 128; t > 0; t >>= 1) {
        if (tid < t) red[tid] += red[tid + t];
        __syncthreads();
    }
    row[tid] = v / red[0];
}

// ---------------- pinv scale ----------------
__global__ void scale_init(float* s) { s[0] = 0.f; s[1] = 0.f; }

__global__ void colrow_max(const float* __restrict__ A2, float* __restrict__ s)
{
    int bh = blockIdx.x, j = threadIdx.x;
    const float* X = A2 + (long long)bh * LM * LM;
    float cs = 0.f, rs = 0.f;
    for (int i = 0; i < LM; ++i) {
        cs += fabsf(X[i * LM + j]);
        rs += fabsf(X[j * LM + i]);
    }
    __shared__ float r1[256], r2[256];
    r1[j] = cs; r2[j] = rs; __syncthreads();
    for (int t = 128; t > 0; t >>= 1) {
        if (j < t) { r1[j] = fmaxf(r1[j], r1[j+t]); r2[j] = fmaxf(r2[j], r2[j+t]); }
        __syncthreads();
    }
    if (j == 0) {
        atomicMax((int*)&s[0], __float_as_int(r1[0]));
        atomicMax((int*)&s[1], __float_as_int(r2[0]));
    }
}

__global__ void make_z0(const float* __restrict__ A2, const float* __restrict__ s,
                        float* __restrict__ Z)
{
    long long idx = (long long)blockIdx.x * 256 + threadIdx.x;
    int c  = idx & 255;
    int r  = (int)((idx >> 8) & 255);
    int bh = (int)(idx >> 16);
    float inv = 1.f / (s[0] * s[1]);
    Z[idx] = A2[(long long)bh * LM * LM + (long long)c * LM + r] * inv;
}

// ---------------- conv + combine ----------------
__global__ void __launch_bounds__(256) conv_combine(
    const float* __restrict__ V, const float* __restrict__ O,
    const float* __restrict__ cw, float* __restrict__ TOK)
{
    int bh = blockIdx.y;
    int h = bh & 7, b = bh >> 3;
    int i0 = blockIdx.x * 64;
    __shared__ float sv[96][64];
    __shared__ float w[KSZ];
    int tid = threadIdx.x;
    if (tid < KSZ) w[tid] = cw[h * KSZ + tid];
    const float* Vb = V + (long long)bh * SEQ * DH;
    for (int e = tid; e < 96 * 64; e += 256) {
        int rr = e >> 6, c = e & 63;
        int gi = i0 - 16 + rr;
        sv[rr][c] = (gi >= 0 && gi < SEQ) ? Vb[(long long)gi * DH + c] : 0.f;
    }
    __syncthreads();
    int c  = tid & 63;
    int ib = tid >> 6;
#pragma unroll 4
    for (int j = 0; j < 16; ++j) {
        int il = ib * 16 + j;
        float acc = O[((long long)bh * SEQ + i0 + il) * DH + c];
#pragma unroll
        for (int t = 0; t < KSZ; ++t) acc += w[t] * sv[il + t][c];
        long long tok = (long long)b * SEQ + i0 + il;
        TOK[tok * DMODEL + h * DH + c] = acc;
    }
}

// ---------------- host driver ----------------
extern "C" void kernel_launch(void* const* d_in, const int* in_sizes, int n_in,
                              void* d_out, int out_size)
{
    const float* x      = (const float*)d_in[0];
    const float* ln_w   = (const float*)d_in[1];
    const float* ln_b   = (const float*)d_in[2];
    const float* w_qkv  = (const float*)d_in[3];
    const float* w_out  = (const float*)d_in[4];
    const float* b_out  = (const float*)d_in[5];
    const float* conv_w = (const float*)d_in[6];
    float* out = (float*)d_out;

    void *p;
    cudaGetSymbolAddress(&p, g_xn);    float* xn  = (float*)p;
    cudaGetSymbolAddress(&p, g_q);     float* Q   = (float*)p;
    cudaGetSymbolAddress(&p, g_k);     float* K   = (float*)p;
    cudaGetSymbolAddress(&p, g_v);     float* V   = (float*)p;
    cudaGetSymbolAddress(&p, g_ql);    float* QL  = (float*)p;
    cudaGetSymbolAddress(&p, g_kl);    float* KL  = (float*)p;
    cudaGetSymbolAddress(&p, g_attn2); float* A2  = (float*)p;
    cudaGetSymbolAddress(&p, g_za);    float* ZA  = (float*)p;
    cudaGetSymbolAddress(&p, g_zb);    float* ZB  = (float*)p;
    cudaGetSymbolAddress(&p, g_xz);    float* XZ  = (float*)p;
    cudaGetSymbolAddress(&p, g_t1);    float* T1  = (float*)p;
    cudaGetSymbolAddress(&p, g_t2);    float* T2  = (float*)p;
    cudaGetSymbolAddress(&p, g_a3v);   float* A3V = (float*)p;
    cudaGetSymbolAddress(&p, g_zav);   float* ZAV = (float*)p;
    cudaGetSymbolAddress(&p, g_outh);  float* OH  = (float*)p;
    cudaGetSymbolAddress(&p, g_tok);   float* TOK = (float*)p;
    cudaGetSymbolAddress(&p, g_pacc);  float* PAC = (float*)p;
    cudaGetSymbolAddress(&p, g_pmax);  float* PMX = (float*)p;
    cudaGetSymbolAddress(&p, g_psum);  float* PSM = (float*)p;
    cudaGetSymbolAddress(&p, g_scale); float* S   = (float*)p;

    const long long sL  = (long long)LM * DH;
    const long long sA2 = (long long)LM * LM;

    const int sav_smem = SAV_SMEM_FLOATS * 4;
    cudaFuncSetAttribute(fused_sav<true>,  cudaFuncAttributeMaxDynamicSharedMemorySize, sav_smem);
    cudaFuncSetAttribute(fused_sav<false>, cudaFuncAttributeMaxDynamicSharedMemorySize, sav_smem);

    // 1. LayerNorm
    ln_kernel<<<NTOK, 128>>>(x, ln_w, ln_b, xn);
    // 2. qkv GEMM with fused head-split epilogue (Q scaled)
    gemm_tc<128,128,2,4,true,1><<<dim3(12, 256, 1), 256>>>(xn, w_qkv, nullptr,
        NTOK, 3*DMODEL, DMODEL, 0, 0, 0, 1.f, 0.f, nullptr, nullptr, nullptr, 0.f, Q, K, V);
    // 3. landmarks
    landmark<<<(BH*LM*DH)/256, 256>>>(Q, QL);
    landmark<<<(BH*LM*DH)/256, 256>>>(K, KL);
    // 4. attn2 = softmax(QL @ KL^T)
    gemm_tc<64,64,2,2,true,0><<<dim3(4, 4, BH), 128>>>(QL, KL, A2,
        LM, LM, DH, sL, sL, sA2, 1.f, 0.f, nullptr, nullptr, nullptr, 0.f, nullptr, nullptr, nullptr);
    softmax_rows<<<BH*LM, 256>>>(A2);
    // 5. pinv init
    scale_init<<<1, 1>>>(S);
    colrow_max<<<BH, 256>>>(A2, S);
    make_z0<<<(BH*LM*LM)/256, 256>>>(A2, S, ZA);
    // 6. Moore-Penrose iterations (diag_sub fused into XZ gemm), 128x128 tiles
    float* Zin = ZA; float* Zout = ZB;
    for (int it = 0; it < 6; ++it) {
        gemm_tc<128,128,2,4,false,2><<<dim3(2,2,BH), 256>>>(A2, Zin, XZ,
            LM, LM, LM, sA2, sA2, sA2, 1.f, 0.f, nullptr, nullptr, T1, 7.f, nullptr, nullptr, nullptr);
        gemm_tc<128,128,2,4,false,0><<<dim3(2,2,BH), 256>>>(XZ, T1, T2,
            LM, LM, LM, sA2, sA2, sA2, -1.f, 15.f, nullptr, nullptr, nullptr, 0.f, nullptr, nullptr, nullptr);
        gemm_tc<128,128,2,4,false,0><<<dim3(2,2,BH), 256>>>(XZ, T2, T1,
            LM, LM, LM, sA2, sA2, sA2, -1.f, 13.f, nullptr, nullptr, nullptr, 0.f, nullptr, nullptr, nullptr);
        gemm_tc<128,128,2,4,false,0><<<dim3(2,2,BH), 256>>>(Zin, T1, Zout,
            LM, LM, LM, sA2, sA2, sA2, 0.25f, 0.f, nullptr, nullptr, nullptr, 0.f, nullptr, nullptr, nullptr);
        float* tmp = Zin; Zin = Zout; Zout = tmp;
    }
    // 7. a3v = softmax(QL @ K^T) @ V  (flash, chunked partials + combine)
    fused_sav<false><<<dim3(LM/64, NCHUNK, BH), 256, sav_smem>>>(QL, K, V,
        PAC, PMX, PSM, LM, SEQ, SEQ/NCHUNK);
    sav_combine<<<(BH*LM*DH)/256, 256>>>(PAC, PMX, PSM, A3V);
    // 8. ZAV = Z @ a3v
    gemm_tc<64,64,2,2,false,0><<<dim3(1, 4, BH), 128>>>(Zin, A3V, ZAV,
        LM, DH, LM, sA2, sL, sL, 1.f, 0.f, nullptr, nullptr, nullptr, 0.f, nullptr, nullptr, nullptr);
    // 9. outh = softmax(Q @ KL^T) @ ZAV (fused, exact)
    fused_sav<true><<<dim3(SEQ/64, 1, BH), 256, sav_smem>>>(Q, KL, ZAV,
        OH, nullptr, nullptr, SEQ, LM, LM);
    // 10. conv residual + combine -> token-major
    conv_combine<<<dim3(SEQ/64, BH), 256>>>(V, OH, conv_w, TOK);
    // 11. final: out = x + TOK @ w_out^T + b_out
    gemm_tc<128,128,2,4,true,0><<<dim3(4, 256, 1), 256>>>(TOK, w_out, out,
        NTOK, DMODEL, DMODEL, 0, 0, 0, 1.f, 0.f, b_out, x, nullptr, 0.f, nullptr, nullptr, nullptr);
}